// round 14
// baseline (speedup 1.0000x reference)
#include <cuda_runtime.h>
#include <cuda_bf16.h>
#include <cstdint>

// ---------------------------------------------------------------------------
// Problem constants
// ---------------------------------------------------------------------------
#define NB    4096
#define DIN   2048
#define HH    1024
#define DD    256
#define NSTEP 15
#define SC    32     // samples per trace CTA

// ---------------------------------------------------------------------------
// Scratch (device globals; no allocation allowed)
// ---------------------------------------------------------------------------
__device__ float g_Z   [2 * NB * DD];    // fp32 Z (z_s | z_e)
__device__ float g_V   [NB * DD];
__device__ float g_mind[NB];
// bf16 hi/lo activations
__device__ __nv_bfloat16 g_Xhi [2 * NB * DIN];
__device__ __nv_bfloat16 g_Xlo [2 * NB * DIN];
__device__ __nv_bfloat16 g_Hhi [2 * NB * HH];
__device__ __nv_bfloat16 g_Hlo [2 * NB * HH];
__device__ __nv_bfloat16 g_Zshi[NB * DD];
__device__ __nv_bfloat16 g_Zslo[NB * DD];
__device__ __nv_bfloat16 g_HWhi[NB * DD];
__device__ __nv_bfloat16 g_HWlo[NB * DD];
// bf16 hi/lo transposed weights [N][K]
__device__ __nv_bfloat16 g_W1Thi[HH * DIN];
__device__ __nv_bfloat16 g_W1Tlo[HH * DIN];
__device__ __nv_bfloat16 g_W2Thi[DD * HH];
__device__ __nv_bfloat16 g_W2Tlo[DD * HH];
__device__ __nv_bfloat16 g_Ww1Thi[DD * DD];
__device__ __nv_bfloat16 g_Ww1Tlo[DD * DD];
__device__ __nv_bfloat16 g_Ww2Thi[DD * DD];
__device__ __nv_bfloat16 g_Ww2Tlo[DD * DD];
// trace weights, bf16 hi/lo: W = Wp1[n][k]; WT = Wp1^T[n][k]
__device__ __nv_bfloat16 g_Wbhi [DD * DD];
__device__ __nv_bfloat16 g_Wblo [DD * DD];
__device__ __nv_bfloat16 g_WTbhi[DD * DD];
__device__ __nv_bfloat16 g_WTblo[DD * DD];

// ---------------------------------------------------------------------------
// Warp-level bf16 MMA
// ---------------------------------------------------------------------------
__device__ __forceinline__ void mma_bf16(float* d, const uint32_t* a,
                                         const uint32_t* b) {
    asm volatile(
        "mma.sync.aligned.m16n8k16.row.col.f32.bf16.bf16.f32 "
        "{%0,%1,%2,%3}, {%4,%5,%6,%7}, {%8,%9}, {%0,%1,%2,%3};"
        : "+f"(d[0]), "+f"(d[1]), "+f"(d[2]), "+f"(d[3])
        : "r"(a[0]), "r"(a[1]), "r"(a[2]), "r"(a[3]), "r"(b[0]), "r"(b[1]));
}

// ---------------------------------------------------------------------------
// Conversions
// ---------------------------------------------------------------------------
__global__ void convX_kernel(const float* __restrict__ xs, const float* __restrict__ xe,
                             __nv_bfloat16* __restrict__ hi, __nv_bfloat16* __restrict__ lo) {
    const size_t i4 = ((size_t)blockIdx.x * blockDim.x + threadIdx.x) * 4;
    const size_t half = (size_t)NB * DIN;
    const float* src = (i4 < half) ? xs + i4 : xe + (i4 - half);
    float4 v = *(const float4*)src;
    float vv[4] = {v.x, v.y, v.z, v.w};
    __nv_bfloat16 h[4], l[4];
#pragma unroll
    for (int j = 0; j < 4; j++) {
        h[j] = __float2bfloat16(vv[j]);
        l[j] = __float2bfloat16(vv[j] - __bfloat162float(h[j]));
    }
    *(uint2*)(hi + i4) = *(uint2*)h;
    *(uint2*)(lo + i4) = *(uint2*)l;
}

// in[K][N] -> transposed hi/lo [N][K]
__global__ void convWT_kernel(const float* __restrict__ in,
                              __nv_bfloat16* __restrict__ hi,
                              __nv_bfloat16* __restrict__ lo, int K, int N) {
    __shared__ float tile[32][33];
    const int n0 = blockIdx.x * 32, k0 = blockIdx.y * 32;
    const int tx = threadIdx.x, ty = threadIdx.y;
    tile[ty][tx] = in[(size_t)(k0 + ty) * N + n0 + tx];
    __syncthreads();
    float v = tile[tx][ty];   // in[k0+tx][n0+ty]
    __nv_bfloat16 h = __float2bfloat16(v);
    __nv_bfloat16 l = __float2bfloat16(v - __bfloat162float(h));
    hi[(size_t)(n0 + ty) * K + k0 + tx] = h;
    lo[(size_t)(n0 + ty) * K + k0 + tx] = l;
}

// Wp1 [256][256] -> W hi/lo ([n][k]) and WT hi/lo (transposed) for the trace
__global__ void prepW_kernel(const float* __restrict__ Wp1,
                             __nv_bfloat16* __restrict__ Whi, __nv_bfloat16* __restrict__ Wlo,
                             __nv_bfloat16* __restrict__ WThi, __nv_bfloat16* __restrict__ WTlo) {
    const int i = blockIdx.x, j = threadIdx.x;
    float w = Wp1[i * DD + j];
    __nv_bfloat16 h = __float2bfloat16(w);
    Whi[i * DD + j] = h;
    Wlo[i * DD + j] = __float2bfloat16(w - __bfloat162float(h));
    float wt = Wp1[j * DD + i];
    __nv_bfloat16 ht = __float2bfloat16(wt);
    WThi[i * DD + j] = ht;
    WTlo[i * DD + j] = __float2bfloat16(wt - __bfloat162float(ht));
}

// ---------------------------------------------------------------------------
// Unified HMMA GEMM (bf16x3 split): C = act(A @ B^T + bias)
// A: [M][K] hi/lo, B: [N][K] hi/lo (transposed weights), K % 64 == 0.
// CTA tile 128x128, 8 warps (4x2), warp tile 32x64, K-chunk 64.
// Outputs: Cf (fp32, optional) and/or Chi/Clo (bf16 split, rows < bfLimit).
// Dynamic smem: 4 tiles x 128 x 72 bf16 = 73728 B.
// ---------------------------------------------------------------------------
#define TS72 72
#define GM_SMEM (4 * 128 * TS72 * 2)

template <int ACT>
__global__ __launch_bounds__(256)
void gemm_mma_kernel(const __nv_bfloat16* __restrict__ Ahi,
                     const __nv_bfloat16* __restrict__ Alo,
                     const __nv_bfloat16* __restrict__ Bhi,
                     const __nv_bfloat16* __restrict__ Blo,
                     const float* __restrict__ bias,
                     float* __restrict__ Cf,
                     __nv_bfloat16* __restrict__ Chi,
                     __nv_bfloat16* __restrict__ Clo,
                     int bfLimit, int N, int K) {
    extern __shared__ __align__(16) __nv_bfloat16 sm4[];
    __nv_bfloat16* Ah = sm4;
    __nv_bfloat16* Al = sm4 + 128 * TS72;
    __nv_bfloat16* Bh = sm4 + 2 * 128 * TS72;
    __nv_bfloat16* Bl = sm4 + 3 * 128 * TS72;

    const int tid  = threadIdx.x;
    const int wid  = tid >> 5;
    const int lane = tid & 31;
    const int n0   = blockIdx.x * 128;
    const int m0   = blockIdx.y * 128;
    const int wm   = (wid & 3) * 32;
    const int wn   = (wid >> 2) * 64;
    const int r    = lane >> 2;
    const int c2   = (lane & 3) * 2;

    float d[2][8][4];
#pragma unroll
    for (int mf = 0; mf < 2; mf++)
#pragma unroll
        for (int nf = 0; nf < 8; nf++)
#pragma unroll
            for (int j = 0; j < 4; j++) d[mf][nf][j] = 0.0f;

    const int NC = K / 64;
    for (int ch = 0; ch < NC; ch++) {
        const int k0 = ch * 64;
        // stage chunk: LDGs issued BEFORE the barrier (overlap prev compute)
        uint4 sAh[4], sAl[4], sBh[4], sBl[4];
#pragma unroll
        for (int i = 0; i < 4; i++) {
            const int u = tid + i * 256;         // 0..1023 per tile
            const int rr = u >> 3;               // 0..127
            const int cc = (u & 7) * 8;          // 0..56
            sAh[i] = *(const uint4*)(Ahi + (size_t)(m0 + rr) * K + k0 + cc);
            sAl[i] = *(const uint4*)(Alo + (size_t)(m0 + rr) * K + k0 + cc);
            sBh[i] = *(const uint4*)(Bhi + (size_t)(n0 + rr) * K + k0 + cc);
            sBl[i] = *(const uint4*)(Blo + (size_t)(n0 + rr) * K + k0 + cc);
        }
        __syncthreads();   // previous chunk's compute done
#pragma unroll
        for (int i = 0; i < 4; i++) {
            const int u = tid + i * 256;
            const int rr = u >> 3;
            const int cc = (u & 7) * 8;
            *(uint4*)(Ah + rr * TS72 + cc) = sAh[i];
            *(uint4*)(Al + rr * TS72 + cc) = sAl[i];
            *(uint4*)(Bh + rr * TS72 + cc) = sBh[i];
            *(uint4*)(Bl + rr * TS72 + cc) = sBl[i];
        }
        __syncthreads();   // tiles visible

#pragma unroll
        for (int kk = 0; kk < 64; kk += 16) {
            uint32_t ah[2][4], al[2][4];
#pragma unroll
            for (int mf = 0; mf < 2; mf++) {
                const int mb = wm + mf * 16;
                ah[mf][0] = *(const uint32_t*)&Ah[(mb + r) * TS72 + kk + c2];
                ah[mf][1] = *(const uint32_t*)&Ah[(mb + r + 8) * TS72 + kk + c2];
                ah[mf][2] = *(const uint32_t*)&Ah[(mb + r) * TS72 + kk + c2 + 8];
                ah[mf][3] = *(const uint32_t*)&Ah[(mb + r + 8) * TS72 + kk + c2 + 8];
                al[mf][0] = *(const uint32_t*)&Al[(mb + r) * TS72 + kk + c2];
                al[mf][1] = *(const uint32_t*)&Al[(mb + r + 8) * TS72 + kk + c2];
                al[mf][2] = *(const uint32_t*)&Al[(mb + r) * TS72 + kk + c2 + 8];
                al[mf][3] = *(const uint32_t*)&Al[(mb + r + 8) * TS72 + kk + c2 + 8];
            }
#pragma unroll
            for (int nf = 0; nf < 8; nf++) {
                const int nb = wn + nf * 8 + r;
                uint32_t bh[2], bl[2];
                bh[0] = *(const uint32_t*)&Bh[nb * TS72 + kk + c2];
                bh[1] = *(const uint32_t*)&Bh[nb * TS72 + kk + c2 + 8];
                bl[0] = *(const uint32_t*)&Bl[nb * TS72 + kk + c2];
                bl[1] = *(const uint32_t*)&Bl[nb * TS72 + kk + c2 + 8];
#pragma unroll
                for (int mf = 0; mf < 2; mf++) {
                    mma_bf16(d[mf][nf], ah[mf], bh);
                    mma_bf16(d[mf][nf], ah[mf], bl);
                    mma_bf16(d[mf][nf], al[mf], bh);
                }
            }
        }
    }

    // epilogue
#pragma unroll
    for (int mf = 0; mf < 2; mf++) {
        const int row = m0 + wm + mf * 16 + r;
#pragma unroll
        for (int nf = 0; nf < 8; nf++) {
            const int col = n0 + wn + nf * 8 + c2;
            const float bb0 = bias[col], bb1 = bias[col + 1];
            float v0 = d[mf][nf][0] + bb0;
            float v1 = d[mf][nf][1] + bb1;
            float v2 = d[mf][nf][2] + bb0;
            float v3 = d[mf][nf][3] + bb1;
            if (ACT) {
                v0 = tanhf(v0); v1 = tanhf(v1); v2 = tanhf(v2); v3 = tanhf(v3);
            }
            if (Cf) {
                float2 p0; p0.x = v0; p0.y = v1;
                float2 p1; p1.x = v2; p1.y = v3;
                *(float2*)&Cf[(size_t)row * N + col] = p0;
                *(float2*)&Cf[(size_t)(row + 8) * N + col] = p1;
            }
            if (Chi) {
                if (row < bfLimit) {
                    __nv_bfloat162 hv, lv;
                    hv.x = __float2bfloat16(v0);
                    hv.y = __float2bfloat16(v1);
                    lv.x = __float2bfloat16(v0 - __bfloat162float(hv.x));
                    lv.y = __float2bfloat16(v1 - __bfloat162float(hv.y));
                    *(__nv_bfloat162*)&Chi[(size_t)row * N + col] = hv;
                    *(__nv_bfloat162*)&Clo[(size_t)row * N + col] = lv;
                }
                if (row + 8 < bfLimit) {
                    __nv_bfloat162 hv, lv;
                    hv.x = __float2bfloat16(v2);
                    hv.y = __float2bfloat16(v3);
                    lv.x = __float2bfloat16(v2 - __bfloat162float(hv.x));
                    lv.y = __float2bfloat16(v3 - __bfloat162float(hv.y));
                    *(__nv_bfloat162*)&Chi[(size_t)(row + 8) * N + col] = hv;
                    *(__nv_bfloat162*)&Clo[(size_t)(row + 8) * N + col] = lv;
                }
            }
        }
    }
}

// ---------------------------------------------------------------------------
__global__ void fallback_kernel(float* __restrict__ V, const float* __restrict__ noise) {
    __shared__ float rw[8], rn[8];
    const int s = blockIdx.x, t = threadIdx.x;
    const int lane = t & 31, warp = t >> 5;
    float w = V[s * DD + t];
    float n = noise[s * DD + t];
    float pw = w * w, pn = n * n;
#pragma unroll
    for (int off = 16; off > 0; off >>= 1) {
        pw += __shfl_xor_sync(0xffffffffu, pw, off);
        pn += __shfl_xor_sync(0xffffffffu, pn, off);
    }
    if (lane == 0) { rw[warp] = pw; rn[warp] = pn; }
    __syncthreads();
    float sw = 0.f, sn = 0.f;
#pragma unroll
    for (int i = 0; i < 8; i++) { sw += rw[i]; sn += rn[i]; }
    float wn = sqrtf(sw + 1e-24f);
    if (wn < 1e-5f) {
        float nn = sqrtf(sn + 1e-24f);
        V[s * DD + t] = w + n / (nn + 1e-12f) * 1e-4f;
    }
}

// ---------------------------------------------------------------------------
// Trace kernel v6 — HMMA bf16x3 (R13 exact). 32 samples/CTA, 128 CTAs.
// ---------------------------------------------------------------------------
#define AK   264
#define WK   40
#define VROW 260
#define O_ALO 16896
#define O_WB  33792
#define O_V   115712
#define O_XA  148992
#define O_VA  182272
#define O_RA  215552
#define O_RB  216576
#define O_BA  217600
#define O_BB  217728
#define TR_SMEM_BYTES 217856

__device__ __forceinline__ void storeA2(__nv_bfloat16* Ahi, __nv_bfloat16* Alo,
                                        int row, int cc, float f0, float f1) {
    __nv_bfloat16 h0 = __float2bfloat16(f0), h1 = __float2bfloat16(f1);
    __nv_bfloat162 hv; hv.x = h0; hv.y = h1;
    *(__nv_bfloat162*)&Ahi[row * AK + cc] = hv;
    __nv_bfloat162 lv;
    lv.x = __float2bfloat16(f0 - __bfloat162float(h0));
    lv.y = __float2bfloat16(f1 - __bfloat162float(h1));
    *(__nv_bfloat162*)&Alo[row * AK + cc] = lv;
}

__global__ __launch_bounds__(256)
void trace_mma_kernel(const float* __restrict__ Z, const float* __restrict__ V,
                      const __nv_bfloat16* __restrict__ Wbhi,
                      const __nv_bfloat16* __restrict__ Wblo,
                      const __nv_bfloat16* __restrict__ WTbhi,
                      const __nv_bfloat16* __restrict__ WTblo,
                      const float* __restrict__ bp1, const float* __restrict__ wp2,
                      float* __restrict__ mind) {
    extern __shared__ __align__(16) char dsm[];
    __nv_bfloat16* Ahi = (__nv_bfloat16*)(dsm);
    __nv_bfloat16* Alo = (__nv_bfloat16*)(dsm + O_ALO);
    float* v_sm  = (float*)(dsm + O_V);
    float* xa_sm = (float*)(dsm + O_XA);
    float* va_sm = (float*)(dsm + O_VA);
    float* red_a = (float*)(dsm + O_RA);
    float* red_b = (float*)(dsm + O_RB);
    float* bc_a  = (float*)(dsm + O_BA);
    float* bc_b  = (float*)(dsm + O_BB);

    const int tid  = threadIdx.x;
    const int wid  = tid >> 5;
    const int lane = tid & 31;
    const int r    = lane >> 2;
    const int c2   = (lane & 3) * 2;
    const int wn   = wid * 32;
    const int s0   = blockIdx.x * SC;
    const float hs = 1.0f / 15.0f;
    const int wrow = tid >> 2;
    const int wcol = (tid & 3) * 8;

    float x[32], vt[32], g[32], d[32];
    float bpr[8], w2r[8];
#pragma unroll
    for (int nf = 0; nf < 4; nf++)
#pragma unroll
        for (int jl = 0; jl < 2; jl++) {
            const int col = wn + nf * 8 + c2 + jl;
            bpr[nf * 2 + jl] = bp1[col];
            w2r[nf * 2 + jl] = wp2[col];
        }

    for (int i = tid; i < SC * DD; i += 256)
        v_sm[(i >> 8) * VROW + (i & 255)] = V[(size_t)(s0 + (i >> 8)) * DD + (i & 255)];
#pragma unroll
    for (int mf = 0; mf < 2; mf++)
#pragma unroll
        for (int nf = 0; nf < 4; nf++)
#pragma unroll
            for (int jp = 0; jp < 2; jp++) {
                const int smp = mf * 16 + r + 8 * jp;
                const int cc = wn + nf * 8 + c2;
                float2 xv = *(const float2*)&Z[(size_t)(s0 + smp) * DD + cc];
                x[mf * 16 + nf * 4 + jp * 2]     = xv.x;
                x[mf * 16 + nf * 4 + jp * 2 + 1] = xv.y;
            }
    float mymin = 3.4e38f;
    __syncthreads();

#define MATVEC(BHI, BLO)                                                       \
    do {                                                                       \
        _Pragma("unroll") for (int e = 0; e < 32; e++) d[e] = 0.f;             \
        uint4 rh[4], rl[4];                                                    \
        _Pragma("unroll") for (int p = 0; p < 4; p++) {                        \
            rh[p] = *(const uint4*)((BHI) + (size_t)(p * 64 + wrow) * DD + wcol); \
            rl[p] = *(const uint4*)((BLO) + (size_t)(p * 64 + wrow) * DD + wcol); \
        }                                                                      \
        {                                                                      \
            __nv_bfloat16* wh = (__nv_bfloat16*)(dsm + O_WB);                  \
            __nv_bfloat16* wl = wh + 10240;                                    \
            _Pragma("unroll") for (int p = 0; p < 4; p++) {                    \
                *(uint4*)(wh + (p * 64 + wrow) * WK + wcol) = rh[p];           \
                *(uint4*)(wl + (p * 64 + wrow) * WK + wcol) = rl[p];           \
            }                                                                  \
        }                                                                      \
        _Pragma("unroll 1") for (int c = 0; c < 8; c++) {                      \
            __syncthreads();                                                   \
            if (c < 7) {                                                       \
                const int k0n = (c + 1) * 32;                                  \
                _Pragma("unroll") for (int p = 0; p < 4; p++) {                \
                    rh[p] = *(const uint4*)((BHI) + (size_t)(p * 64 + wrow) * DD + k0n + wcol); \
                    rl[p] = *(const uint4*)((BLO) + (size_t)(p * 64 + wrow) * DD + k0n + wcol); \
                }                                                              \
            }                                                                  \
            const __nv_bfloat16* wbh =                                         \
                (const __nv_bfloat16*)(dsm + O_WB + (c & 1) * 40960);          \
            const __nv_bfloat16* wbl = wbh + 10240;                            \
            const int k0 = c * 32;                                             \
            _Pragma("unroll") for (int kk = 0; kk < 32; kk += 16) {            \
                uint32_t ah[2][4], al[2][4];                                   \
                _Pragma("unroll") for (int mf = 0; mf < 2; mf++) {             \
                    const int mr = mf * 16 + r;                                \
                    ah[mf][0] = *(const uint32_t*)&Ahi[mr * AK + k0 + kk + c2]; \
                    ah[mf][1] = *(const uint32_t*)&Ahi[(mr + 8) * AK + k0 + kk + c2]; \
                    ah[mf][2] = *(const uint32_t*)&Ahi[mr * AK + k0 + kk + c2 + 8]; \
                    ah[mf][3] = *(const uint32_t*)&Ahi[(mr + 8) * AK + k0 + kk + c2 + 8]; \
                    al[mf][0] = *(const uint32_t*)&Alo[mr * AK + k0 + kk + c2]; \
                    al[mf][1] = *(const uint32_t*)&Alo[(mr + 8) * AK + k0 + kk + c2]; \
                    al[mf][2] = *(const uint32_t*)&Alo[mr * AK + k0 + kk + c2 + 8]; \
                    al[mf][3] = *(const uint32_t*)&Alo[(mr + 8) * AK + k0 + kk + c2 + 8]; \
                }                                                              \
                _Pragma("unroll") for (int nf = 0; nf < 4; nf++) {             \
                    const int nb = wn + nf * 8 + r;                            \
                    uint32_t bh[2], bl[2];                                     \
                    bh[0] = *(const uint32_t*)&wbh[nb * WK + kk + c2];         \
                    bh[1] = *(const uint32_t*)&wbh[nb * WK + kk + c2 + 8];     \
                    bl[0] = *(const uint32_t*)&wbl[nb * WK + kk + c2];         \
                    bl[1] = *(const uint32_t*)&wbl[nb * WK + kk + c2 + 8];     \
                    _Pragma("unroll") for (int mf = 0; mf < 2; mf++) {         \
                        mma_bf16(&d[mf * 16 + nf * 4], ah[mf], bh);            \
                        mma_bf16(&d[mf * 16 + nf * 4], ah[mf], bl);            \
                        mma_bf16(&d[mf * 16 + nf * 4], al[mf], bh);            \
                    }                                                          \
                }                                                              \
            }                                                                  \
            if (c < 7) {                                                       \
                __nv_bfloat16* wsh =                                           \
                    (__nv_bfloat16*)(dsm + O_WB + ((c + 1) & 1) * 40960);      \
                __nv_bfloat16* wsl = wsh + 10240;                              \
                _Pragma("unroll") for (int p = 0; p < 4; p++) {                \
                    *(uint4*)(wsh + (p * 64 + wrow) * WK + wcol) = rh[p];      \
                    *(uint4*)(wsl + (p * 64 + wrow) * WK + wcol) = rl[p];      \
                }                                                              \
            }                                                                  \
        }                                                                      \
        __syncthreads();                                                       \
    } while (0)

#define ACCEL()                                                                \
    do {                                                                       \
        __syncthreads();                                                       \
        MATVEC(WTbhi, WTblo);                                                  \
        _Pragma("unroll") for (int mf = 0; mf < 2; mf++)                       \
        _Pragma("unroll") for (int nf = 0; nf < 4; nf++)                       \
        _Pragma("unroll") for (int jp = 0; jp < 2; jp++) {                     \
            const int e0 = mf * 16 + nf * 4 + jp * 2;                          \
            float h0 = tanhf(d[e0] + bpr[nf * 2]);                             \
            float h1 = tanhf(d[e0 + 1] + bpr[nf * 2 + 1]);                     \
            float sv0 = (1.0f - h0 * h0) * w2r[nf * 2];                        \
            float sv1 = (1.0f - h1 * h1) * w2r[nf * 2 + 1];                    \
            storeA2(Ahi, Alo, mf * 16 + r + 8 * jp, wn + nf * 8 + c2, sv0, sv1); \
        }                                                                      \
        __syncthreads();                                                       \
        MATVEC(Wbhi, Wblo);                                                    \
        {                                                                      \
            float pg[4] = {0.f, 0.f, 0.f, 0.f};                                \
            float pv[4] = {0.f, 0.f, 0.f, 0.f};                                \
            _Pragma("unroll") for (int mf = 0; mf < 2; mf++)                   \
            _Pragma("unroll") for (int nf = 0; nf < 4; nf++)                   \
            _Pragma("unroll") for (int j = 0; j < 4; j++) {                    \
                const int e = mf * 16 + nf * 4 + j;                            \
                const int sl = mf * 2 + (j >> 1);                              \
                pg[sl] += d[e] * vt[e];                                        \
                pv[sl] += vt[e] * vt[e];                                       \
            }                                                                  \
            _Pragma("unroll") for (int sl = 0; sl < 4; sl++) {                 \
                pg[sl] += __shfl_xor_sync(0xffffffffu, pg[sl], 1);             \
                pg[sl] += __shfl_xor_sync(0xffffffffu, pg[sl], 2);             \
                pv[sl] += __shfl_xor_sync(0xffffffffu, pv[sl], 1);             \
                pv[sl] += __shfl_xor_sync(0xffffffffu, pv[sl], 2);             \
            }                                                                  \
            if ((lane & 3) == 0) {                                             \
                _Pragma("unroll") for (int sl = 0; sl < 4; sl++) {             \
                    const int row = (sl >> 1) * 16 + r + 8 * (sl & 1);         \
                    red_a[wid * 32 + row] = pg[sl];                            \
                    red_b[wid * 32 + row] = pv[sl];                            \
                }                                                              \
            }                                                                  \
        }                                                                      \
        __syncthreads();                                                       \
        if (tid < 32) {                                                        \
            float sg = 0.f;                                                    \
            float sv2 = 0.f;                                                   \
            _Pragma("unroll") for (int w8 = 0; w8 < 8; w8++) {                 \
                sg += red_a[w8 * 32 + tid];                                    \
                sv2 += red_b[w8 * 32 + tid];                                   \
            }                                                                  \
            bc_a[tid] = sg;                                                    \
            bc_b[tid] = sv2;                                                   \
        }                                                                      \
        __syncthreads();                                                       \
        _Pragma("unroll") for (int mf = 0; mf < 2; mf++)                       \
        _Pragma("unroll") for (int nf = 0; nf < 4; nf++)                       \
        _Pragma("unroll") for (int j = 0; j < 4; j++) {                        \
            const int e = mf * 16 + nf * 4 + j;                                \
            const int smp = mf * 16 + r + 8 * (j >> 1);                        \
            g[e] = 0.5f * bc_b[smp] * d[e] - bc_a[smp] * vt[e];                \
        }                                                                      \
    } while (0)

#define FOR_PAIR(...)                                                          \
    _Pragma("unroll") for (int mf = 0; mf < 2; mf++)                           \
    _Pragma("unroll") for (int nf = 0; nf < 4; nf++)                           \
    _Pragma("unroll") for (int jp = 0; jp < 2; jp++) {                         \
        const int e0 = mf * 16 + nf * 4 + jp * 2;                              \
        const int row = mf * 16 + r + 8 * jp;                                  \
        const int cc = wn + nf * 8 + c2;                                       \
        const int vidx = row * VROW + cc;                                      \
        (void)e0; (void)row; (void)cc; (void)vidx;                             \
        __VA_ARGS__                                                            \
    }

    for (int step = 0; step < NSTEP; step++) {
        FOR_PAIR({
            float2 vv = *(float2*)&v_sm[vidx];
            vt[e0] = vv.x; vt[e0 + 1] = vv.y;
            storeA2(Ahi, Alo, row, cc, x[e0], x[e0 + 1]);
        })
        ACCEL();
        FOR_PAIR({
            float2 t0; t0.x = vt[e0]; t0.y = vt[e0 + 1];
            *(float2*)&xa_sm[vidx] = t0;
            float2 t1; t1.x = g[e0]; t1.y = g[e0 + 1];
            *(float2*)&va_sm[vidx] = t1;
        })
        FOR_PAIR({
            storeA2(Ahi, Alo, row, cc,
                    x[e0] + 0.5f * hs * vt[e0], x[e0 + 1] + 0.5f * hs * vt[e0 + 1]);
            vt[e0]     += 0.5f * hs * g[e0];
            vt[e0 + 1] += 0.5f * hs * g[e0 + 1];
        })
        ACCEL();
        FOR_PAIR({
            float2 xv = *(float2*)&xa_sm[vidx];
            xv.x += 2.0f * vt[e0]; xv.y += 2.0f * vt[e0 + 1];
            *(float2*)&xa_sm[vidx] = xv;
            float2 av = *(float2*)&va_sm[vidx];
            av.x += 2.0f * g[e0]; av.y += 2.0f * g[e0 + 1];
            *(float2*)&va_sm[vidx] = av;
        })
        FOR_PAIR({
            storeA2(Ahi, Alo, row, cc,
                    x[e0] + 0.5f * hs * vt[e0], x[e0 + 1] + 0.5f * hs * vt[e0 + 1]);
            float2 vv = *(float2*)&v_sm[vidx];
            vt[e0]     = vv.x + 0.5f * hs * g[e0];
            vt[e0 + 1] = vv.y + 0.5f * hs * g[e0 + 1];
        })
        ACCEL();
        FOR_PAIR({
            float2 xv = *(float2*)&xa_sm[vidx];
            xv.x += 2.0f * vt[e0]; xv.y += 2.0f * vt[e0 + 1];
            *(float2*)&xa_sm[vidx] = xv;
            float2 av = *(float2*)&va_sm[vidx];
            av.x += 2.0f * g[e0]; av.y += 2.0f * g[e0 + 1];
            *(float2*)&va_sm[vidx] = av;
        })
        FOR_PAIR({
            storeA2(Ahi, Alo, row, cc,
                    x[e0] + hs * vt[e0], x[e0 + 1] + hs * vt[e0 + 1]);
            float2 vv = *(float2*)&v_sm[vidx];
            vt[e0]     = vv.x + hs * g[e0];
            vt[e0 + 1] = vv.y + hs * g[e0 + 1];
        })
        ACCEL();
        {
            float pd[4] = {0.f, 0.f, 0.f, 0.f};
            FOR_PAIR({
                float2 xav = *(float2*)&xa_sm[vidx];
                float2 vav = *(float2*)&va_sm[vidx];
                float2 vv  = *(float2*)&v_sm[vidx];
                x[e0]     += (hs / 6.0f) * (xav.x + vt[e0]);
                x[e0 + 1] += (hs / 6.0f) * (xav.y + vt[e0 + 1]);
                vv.x += (hs / 6.0f) * (vav.x + g[e0]);
                vv.y += (hs / 6.0f) * (vav.y + g[e0 + 1]);
                *(float2*)&v_sm[vidx] = vv;
                float2 zev = *(const float2*)&Z[(size_t)(NB + s0 + row) * DD + cc];
                float dd0 = x[e0] - zev.x;
                float dd1 = x[e0 + 1] - zev.y;
                pd[mf * 2 + jp] += dd0 * dd0 + dd1 * dd1;
            })
#pragma unroll
            for (int sl = 0; sl < 4; sl++) {
                pd[sl] += __shfl_xor_sync(0xffffffffu, pd[sl], 1);
                pd[sl] += __shfl_xor_sync(0xffffffffu, pd[sl], 2);
            }
            if ((lane & 3) == 0) {
#pragma unroll
                for (int sl = 0; sl < 4; sl++) {
                    const int row = (sl >> 1) * 16 + r + 8 * (sl & 1);
                    red_a[wid * 32 + row] = pd[sl];
                }
            }
            __syncthreads();
            if (tid < 32) {
                float tot = 0.f;
#pragma unroll
                for (int w8 = 0; w8 < 8; w8++) tot += red_a[w8 * 32 + tid];
                mymin = fminf(mymin, tot);
            }
            __syncthreads();
        }
    }

    if (tid < 32) mind[s0 + tid] = mymin;
#undef FOR_PAIR
#undef ACCEL
#undef MATVEC
}

// ---------------------------------------------------------------------------
__global__ void reduce_kernel(const float* __restrict__ mind, float* __restrict__ out) {
    __shared__ float sm[1024];
    const int t = threadIdx.x;
    float a = mind[t] + mind[t + 1024] + mind[t + 2048] + mind[t + 3072];
    sm[t] = a;
    __syncthreads();
    for (int off = 512; off > 0; off >>= 1) {
        if (t < off) sm[t] += sm[t + off];
        __syncthreads();
    }
    if (t == 0) out[0] = sm[0] * (1.0f / (float)NB);
}

// ---------------------------------------------------------------------------
// Launch
// ---------------------------------------------------------------------------
extern "C" void kernel_launch(void* const* d_in, const int* in_sizes, int n_in,
                              void* d_out, int out_size) {
    const float* x_start = (const float*)d_in[0];
    const float* x_end   = (const float*)d_in[1];
    const float* noise   = (const float*)d_in[2];
    const float* W1  = (const float*)d_in[3];
    const float* b1  = (const float*)d_in[4];
    const float* W2  = (const float*)d_in[5];
    const float* b2  = (const float*)d_in[6];
    const float* Ww1 = (const float*)d_in[7];
    const float* bw1 = (const float*)d_in[8];
    const float* Ww2 = (const float*)d_in[9];
    const float* bw2 = (const float*)d_in[10];
    const float* Wp1 = (const float*)d_in[11];
    const float* bp1 = (const float*)d_in[12];
    const float* wp2 = (const float*)d_in[13];

    float *Zb, *Vb, *Md;
    cudaGetSymbolAddress((void**)&Zb, g_Z);
    cudaGetSymbolAddress((void**)&Vb, g_V);
    cudaGetSymbolAddress((void**)&Md, g_mind);
    __nv_bfloat16 *Xhi, *Xlo, *Hhi, *Hlo, *Zshi, *Zslo, *HWhi, *HWlo;
    __nv_bfloat16 *W1h, *W1l, *W2h, *W2l, *Ww1h, *Ww1l, *Ww2h, *Ww2l;
    __nv_bfloat16 *Wph, *Wpl, *WTh, *WTl;
    cudaGetSymbolAddress((void**)&Xhi,  g_Xhi);
    cudaGetSymbolAddress((void**)&Xlo,  g_Xlo);
    cudaGetSymbolAddress((void**)&Hhi,  g_Hhi);
    cudaGetSymbolAddress((void**)&Hlo,  g_Hlo);
    cudaGetSymbolAddress((void**)&Zshi, g_Zshi);
    cudaGetSymbolAddress((void**)&Zslo, g_Zslo);
    cudaGetSymbolAddress((void**)&HWhi, g_HWhi);
    cudaGetSymbolAddress((void**)&HWlo, g_HWlo);
    cudaGetSymbolAddress((void**)&W1h,  g_W1Thi);
    cudaGetSymbolAddress((void**)&W1l,  g_W1Tlo);
    cudaGetSymbolAddress((void**)&W2h,  g_W2Thi);
    cudaGetSymbolAddress((void**)&W2l,  g_W2Tlo);
    cudaGetSymbolAddress((void**)&Ww1h, g_Ww1Thi);
    cudaGetSymbolAddress((void**)&Ww1l, g_Ww1Tlo);
    cudaGetSymbolAddress((void**)&Ww2h, g_Ww2Thi);
    cudaGetSymbolAddress((void**)&Ww2l, g_Ww2Tlo);
    cudaGetSymbolAddress((void**)&Wph,  g_Wbhi);
    cudaGetSymbolAddress((void**)&Wpl,  g_Wblo);
    cudaGetSymbolAddress((void**)&WTh,  g_WTbhi);
    cudaGetSymbolAddress((void**)&WTl,  g_WTblo);

    cudaFuncSetAttribute(gemm_mma_kernel<0>,
                         cudaFuncAttributeMaxDynamicSharedMemorySize, GM_SMEM);
    cudaFuncSetAttribute(gemm_mma_kernel<1>,
                         cudaFuncAttributeMaxDynamicSharedMemorySize, GM_SMEM);
    cudaFuncSetAttribute(trace_mma_kernel,
                         cudaFuncAttributeMaxDynamicSharedMemorySize, TR_SMEM_BYTES);

    // conversions
    convX_kernel<<<(2 * NB * DIN / 4) / 256, 256>>>(x_start, x_end, Xhi, Xlo);
    convWT_kernel<<<dim3(HH / 32, DIN / 32), dim3(32, 32)>>>(W1, W1h, W1l, DIN, HH);
    convWT_kernel<<<dim3(DD / 32, HH / 32), dim3(32, 32)>>>(W2, W2h, W2l, HH, DD);
    convWT_kernel<<<dim3(DD / 32, DD / 32), dim3(32, 32)>>>(Ww1, Ww1h, Ww1l, DD, DD);
    convWT_kernel<<<dim3(DD / 32, DD / 32), dim3(32, 32)>>>(Ww2, Ww2h, Ww2l, DD, DD);
    prepW_kernel<<<DD, DD>>>(Wp1, Wph, Wpl, WTh, WTl);

    // enc1: Hb = tanh(X @ W1 + b1)  (bf16 hi/lo out only)
    gemm_mma_kernel<1><<<dim3(HH / 128, 2 * NB / 128), 256, GM_SMEM>>>(
        Xhi, Xlo, W1h, W1l, b1, nullptr, Hhi, Hlo, 2 * NB, HH, DIN);
    // enc2: Z = Hb @ W2 + b2  (fp32 full; z_s rows also bf16 hi/lo)
    gemm_mma_kernel<0><<<dim3(DD / 128, 2 * NB / 128), 256, GM_SMEM>>>(
        Hhi, Hlo, W2h, W2l, b2, Zb, Zshi, Zslo, NB, DD, HH);
    // wind1: HW = tanh(z_s @ Ww1 + bw1)  (bf16 hi/lo out)
    gemm_mma_kernel<1><<<dim3(DD / 128, NB / 128), 256, GM_SMEM>>>(
        Zshi, Zslo, Ww1h, Ww1l, bw1, nullptr, HWhi, HWlo, NB, DD, DD);
    // wind2: V = HW @ Ww2 + bw2  (fp32 out)
    gemm_mma_kernel<0><<<dim3(DD / 128, NB / 128), 256, GM_SMEM>>>(
        HWhi, HWlo, Ww2h, Ww2l, bw2, Vb, nullptr, nullptr, 0, DD, DD);

    fallback_kernel<<<NB, DD>>>(Vb, noise);
    trace_mma_kernel<<<NB / SC, 256, TR_SMEM_BYTES>>>(
        Zb, Vb, Wph, Wpl, WTh, WTl, bp1, wp2, Md);
    reduce_kernel<<<1, 1024>>>(Md, (float*)d_out);
}

// round 15
// speedup vs baseline: 1.0590x; 1.0590x over previous
#include <cuda_runtime.h>
#include <cuda_bf16.h>
#include <cstdint>

// ---------------------------------------------------------------------------
// Problem constants
// ---------------------------------------------------------------------------
#define NB    4096
#define DIN   2048
#define HH    1024
#define DD    256
#define NSTEP 15
#define SC    32     // samples per trace CTA

// ---------------------------------------------------------------------------
// Scratch (device globals; no allocation allowed)
// ---------------------------------------------------------------------------
__device__ float g_Z   [2 * NB * DD];    // fp32 Z (z_s | z_e)
__device__ float g_V   [NB * DD];
__device__ float g_mind[NB];
__device__ __nv_bfloat16 g_Xhi [2 * NB * DIN];
__device__ __nv_bfloat16 g_Xlo [2 * NB * DIN];
__device__ __nv_bfloat16 g_Hhi [2 * NB * HH];
__device__ __nv_bfloat16 g_Hlo [2 * NB * HH];
__device__ __nv_bfloat16 g_Zshi[NB * DD];
__device__ __nv_bfloat16 g_Zslo[NB * DD];
__device__ __nv_bfloat16 g_HWhi[NB * DD];
__device__ __nv_bfloat16 g_HWlo[NB * DD];
__device__ __nv_bfloat16 g_W1Thi[HH * DIN];
__device__ __nv_bfloat16 g_W1Tlo[HH * DIN];
__device__ __nv_bfloat16 g_W2Thi[DD * HH];
__device__ __nv_bfloat16 g_W2Tlo[DD * HH];
__device__ __nv_bfloat16 g_Ww1Thi[DD * DD];
__device__ __nv_bfloat16 g_Ww1Tlo[DD * DD];
__device__ __nv_bfloat16 g_Ww2Thi[DD * DD];
__device__ __nv_bfloat16 g_Ww2Tlo[DD * DD];
__device__ __nv_bfloat16 g_Wbhi [DD * DD];
__device__ __nv_bfloat16 g_Wblo [DD * DD];
__device__ __nv_bfloat16 g_WTbhi[DD * DD];
__device__ __nv_bfloat16 g_WTblo[DD * DD];

// ---------------------------------------------------------------------------
// Warp-level bf16 MMA
// ---------------------------------------------------------------------------
__device__ __forceinline__ void mma_bf16(float* d, const uint32_t* a,
                                         const uint32_t* b) {
    asm volatile(
        "mma.sync.aligned.m16n8k16.row.col.f32.bf16.bf16.f32 "
        "{%0,%1,%2,%3}, {%4,%5,%6,%7}, {%8,%9}, {%0,%1,%2,%3};"
        : "+f"(d[0]), "+f"(d[1]), "+f"(d[2]), "+f"(d[3])
        : "r"(a[0]), "r"(a[1]), "r"(a[2]), "r"(a[3]), "r"(b[0]), "r"(b[1]));
}

// ---------------------------------------------------------------------------
// Mega conversion kernel (ONE launch). 256 threads/block. Sections:
//  [0, XB)                     : X (start|end) -> bf16 hi/lo     (4 floats/thr)
//  [XB, XB+2048)               : W1  [2048][1024] -> W1T hi/lo   (32x32 tiles)
//  [+256)                      : W2  [1024][256]  -> W2T
//  [+64)                       : Ww1 [256][256]   -> Ww1T
//  [+64)                       : Ww2 [256][256]   -> Ww2T
//  [+64)                       : Wp1 -> Wb (direct) + WTb (transposed)
// ---------------------------------------------------------------------------
#define XB    (2 * NB * DIN / (256 * 4))        // 16384
#define TB_W1 2048
#define TB_W2 256
#define TB_WW 64

__device__ __forceinline__ void split_bf16(float v, __nv_bfloat16& h, __nv_bfloat16& l) {
    h = __float2bfloat16(v);
    l = __float2bfloat16(v - __bfloat162float(h));
}

__device__ void conv_tileT(const float* __restrict__ in,
                           __nv_bfloat16* __restrict__ hi,
                           __nv_bfloat16* __restrict__ lo,
                           int K, int N, int tileIdx) {
    // in[K][N]; out transposed hi/lo [N][K]. tile = 32x32.
    __shared__ float tile[32][33];
    const int ntiles_n = N / 32;
    const int k0 = (tileIdx / ntiles_n) * 32;
    const int n0 = (tileIdx % ntiles_n) * 32;
    const int tx = threadIdx.x & 31;
    const int ty4 = (threadIdx.x >> 5) * 4;
#pragma unroll
    for (int i = 0; i < 4; i++)
        tile[ty4 + i][tx] = in[(size_t)(k0 + ty4 + i) * N + n0 + tx];
    __syncthreads();
#pragma unroll
    for (int i = 0; i < 4; i++) {
        float v = tile[tx][ty4 + i];           // in[k0+tx][n0+ty4+i]
        __nv_bfloat16 h, l; split_bf16(v, h, l);
        hi[(size_t)(n0 + ty4 + i) * K + k0 + tx] = h;
        lo[(size_t)(n0 + ty4 + i) * K + k0 + tx] = l;
    }
}

__global__ __launch_bounds__(256)
void conv_all_kernel(const float* __restrict__ xs, const float* __restrict__ xe,
                     const float* __restrict__ W1, const float* __restrict__ W2,
                     const float* __restrict__ Ww1, const float* __restrict__ Ww2,
                     const float* __restrict__ Wp1,
                     __nv_bfloat16* __restrict__ Xhi, __nv_bfloat16* __restrict__ Xlo,
                     __nv_bfloat16* __restrict__ W1h, __nv_bfloat16* __restrict__ W1l,
                     __nv_bfloat16* __restrict__ W2h, __nv_bfloat16* __restrict__ W2l,
                     __nv_bfloat16* __restrict__ Ww1h, __nv_bfloat16* __restrict__ Ww1l,
                     __nv_bfloat16* __restrict__ Ww2h, __nv_bfloat16* __restrict__ Ww2l,
                     __nv_bfloat16* __restrict__ Wph, __nv_bfloat16* __restrict__ Wpl,
                     __nv_bfloat16* __restrict__ WTh, __nv_bfloat16* __restrict__ WTl) {
    int b = blockIdx.x;
    if (b < XB) {
        const size_t i4 = ((size_t)b * 256 + threadIdx.x) * 4;
        const size_t half = (size_t)NB * DIN;
        const float* src = (i4 < half) ? xs + i4 : xe + (i4 - half);
        float4 v = *(const float4*)src;
        float vv[4] = {v.x, v.y, v.z, v.w};
        __nv_bfloat16 h[4], l[4];
#pragma unroll
        for (int j = 0; j < 4; j++) split_bf16(vv[j], h[j], l[j]);
        *(uint2*)(Xhi + i4) = *(uint2*)h;
        *(uint2*)(Xlo + i4) = *(uint2*)l;
        return;
    }
    b -= XB;
    if (b < TB_W1) { conv_tileT(W1, W1h, W1l, DIN, HH, b); return; }
    b -= TB_W1;
    if (b < TB_W2) { conv_tileT(W2, W2h, W2l, HH, DD, b); return; }
    b -= TB_W2;
    if (b < TB_WW) { conv_tileT(Ww1, Ww1h, Ww1l, DD, DD, b); return; }
    b -= TB_WW;
    if (b < TB_WW) { conv_tileT(Ww2, Ww2h, Ww2l, DD, DD, b); return; }
    b -= TB_WW;
    {
        // Wp1 -> Wb (direct [i][j]) and WTb (transposed), 32x32 tile
        __shared__ float tile[32][33];
        const int i0 = (b / 8) * 32;
        const int j0 = (b % 8) * 32;
        const int tx = threadIdx.x & 31;
        const int ty4 = (threadIdx.x >> 5) * 4;
#pragma unroll
        for (int i = 0; i < 4; i++) {
            float w = Wp1[(size_t)(i0 + ty4 + i) * DD + j0 + tx];
            tile[ty4 + i][tx] = w;
            __nv_bfloat16 h, l; split_bf16(w, h, l);
            Wph[(size_t)(i0 + ty4 + i) * DD + j0 + tx] = h;
            Wpl[(size_t)(i0 + ty4 + i) * DD + j0 + tx] = l;
        }
        __syncthreads();
#pragma unroll
        for (int i = 0; i < 4; i++) {
            float w = tile[tx][ty4 + i];       // Wp1[i0+tx][j0+ty4+i]
            __nv_bfloat16 h, l; split_bf16(w, h, l);
            WTh[(size_t)(j0 + ty4 + i) * DD + i0 + tx] = h;
            WTl[(size_t)(j0 + ty4 + i) * DD + i0 + tx] = l;
        }
    }
}

// ---------------------------------------------------------------------------
// Unified HMMA GEMM (bf16x3), R11-proven chunk-32 structure, fused epilogue.
// A: [M][K] hi/lo, B: [N][K] hi/lo. CTA 128x128, 8 warps 4x2, K-chunk 32.
// ---------------------------------------------------------------------------
#define TSTR 40

__device__ __forceinline__ void gm_load_tile(__nv_bfloat16* s,
                                             const __nv_bfloat16* __restrict__ g,
                                             int row0, int k0, int K, int tid) {
#pragma unroll
    for (int i = 0; i < 2; i++) {
        const int cid = tid + i * 256;
        const int r = cid >> 2;
        const int c = (cid & 3) * 8;
        uint4 v = *(const uint4*)(g + (size_t)(row0 + r) * K + k0 + c);
        *(uint4*)(s + r * TSTR + c) = v;
    }
}

template <int ACT>
__global__ __launch_bounds__(256, 2)
void gemm_mma_kernel(const __nv_bfloat16* __restrict__ Ahi,
                     const __nv_bfloat16* __restrict__ Alo,
                     const __nv_bfloat16* __restrict__ Bhi,
                     const __nv_bfloat16* __restrict__ Blo,
                     const float* __restrict__ bias,
                     float* __restrict__ Cf,
                     __nv_bfloat16* __restrict__ Chi,
                     __nv_bfloat16* __restrict__ Clo,
                     int bfLimit, int N, int K) {
    __shared__ __align__(16) __nv_bfloat16 Ah[128 * TSTR];
    __shared__ __align__(16) __nv_bfloat16 Al[128 * TSTR];
    __shared__ __align__(16) __nv_bfloat16 Bh[128 * TSTR];
    __shared__ __align__(16) __nv_bfloat16 Bl[128 * TSTR];

    const int tid  = threadIdx.x;
    const int wid  = tid >> 5;
    const int lane = tid & 31;
    const int n0   = blockIdx.x * 128;
    const int m0   = blockIdx.y * 128;
    const int wm   = (wid & 3) * 32;
    const int wn   = (wid >> 2) * 64;
    const int r    = lane >> 2;
    const int c2   = (lane & 3) * 2;

    float d[2][8][4];
#pragma unroll
    for (int mf = 0; mf < 2; mf++)
#pragma unroll
        for (int nf = 0; nf < 8; nf++)
#pragma unroll
            for (int j = 0; j < 4; j++) d[mf][nf][j] = 0.0f;

    for (int ch = 0; ch < K / 32; ch++) {
        const int k0 = ch * 32;
        __syncthreads();
        gm_load_tile(Ah, Ahi, m0, k0, K, tid);
        gm_load_tile(Al, Alo, m0, k0, K, tid);
        gm_load_tile(Bh, Bhi, n0, k0, K, tid);
        gm_load_tile(Bl, Blo, n0, k0, K, tid);
        __syncthreads();

#pragma unroll
        for (int kk = 0; kk < 32; kk += 16) {
            uint32_t ah[2][4], al[2][4];
#pragma unroll
            for (int mf = 0; mf < 2; mf++) {
                const int mb = wm + mf * 16;
                ah[mf][0] = *(const uint32_t*)&Ah[(mb + r) * TSTR + kk + c2];
                ah[mf][1] = *(const uint32_t*)&Ah[(mb + r + 8) * TSTR + kk + c2];
                ah[mf][2] = *(const uint32_t*)&Ah[(mb + r) * TSTR + kk + c2 + 8];
                ah[mf][3] = *(const uint32_t*)&Ah[(mb + r + 8) * TSTR + kk + c2 + 8];
                al[mf][0] = *(const uint32_t*)&Al[(mb + r) * TSTR + kk + c2];
                al[mf][1] = *(const uint32_t*)&Al[(mb + r + 8) * TSTR + kk + c2];
                al[mf][2] = *(const uint32_t*)&Al[(mb + r) * TSTR + kk + c2 + 8];
                al[mf][3] = *(const uint32_t*)&Al[(mb + r + 8) * TSTR + kk + c2 + 8];
            }
#pragma unroll
            for (int nf = 0; nf < 8; nf++) {
                const int nb = wn + nf * 8 + r;
                uint32_t bh[2], bl[2];
                bh[0] = *(const uint32_t*)&Bh[nb * TSTR + kk + c2];
                bh[1] = *(const uint32_t*)&Bh[nb * TSTR + kk + c2 + 8];
                bl[0] = *(const uint32_t*)&Bl[nb * TSTR + kk + c2];
                bl[1] = *(const uint32_t*)&Bl[nb * TSTR + kk + c2 + 8];
#pragma unroll
                for (int mf = 0; mf < 2; mf++) {
                    mma_bf16(d[mf][nf], ah[mf], bh);
                    mma_bf16(d[mf][nf], ah[mf], bl);
                    mma_bf16(d[mf][nf], al[mf], bh);
                }
            }
        }
    }

    // fused epilogue
#pragma unroll
    for (int mf = 0; mf < 2; mf++) {
        const int row = m0 + wm + mf * 16 + r;
#pragma unroll
        for (int nf = 0; nf < 8; nf++) {
            const int col = n0 + wn + nf * 8 + c2;
            const float bb0 = bias[col], bb1 = bias[col + 1];
            float v0 = d[mf][nf][0] + bb0;
            float v1 = d[mf][nf][1] + bb1;
            float v2 = d[mf][nf][2] + bb0;
            float v3 = d[mf][nf][3] + bb1;
            if (ACT) { v0 = tanhf(v0); v1 = tanhf(v1); v2 = tanhf(v2); v3 = tanhf(v3); }
            if (Cf) {
                float2 p0; p0.x = v0; p0.y = v1;
                float2 p1; p1.x = v2; p1.y = v3;
                *(float2*)&Cf[(size_t)row * N + col] = p0;
                *(float2*)&Cf[(size_t)(row + 8) * N + col] = p1;
            }
            if (Chi) {
                if (row < bfLimit) {
                    __nv_bfloat162 hv, lv;
                    split_bf16(v0, hv.x, lv.x);
                    split_bf16(v1, hv.y, lv.y);
                    *(__nv_bfloat162*)&Chi[(size_t)row * N + col] = hv;
                    *(__nv_bfloat162*)&Clo[(size_t)row * N + col] = lv;
                }
                if (row + 8 < bfLimit) {
                    __nv_bfloat162 hv, lv;
                    split_bf16(v2, hv.x, lv.x);
                    split_bf16(v3, hv.y, lv.y);
                    *(__nv_bfloat162*)&Chi[(size_t)(row + 8) * N + col] = hv;
                    *(__nv_bfloat162*)&Clo[(size_t)(row + 8) * N + col] = lv;
                }
            }
        }
    }
}

// ---------------------------------------------------------------------------
// Trace kernel v6 (R13) + folded degenerate-wind fallback.
// ---------------------------------------------------------------------------
#define AK   264
#define WK   40
#define VROW 260
#define O_ALO 16896
#define O_WB  33792
#define O_V   115712
#define O_XA  148992
#define O_VA  182272
#define O_RA  215552
#define O_RB  216576
#define O_BA  217600
#define O_BB  217728
#define TR_SMEM_BYTES 217856

__device__ __forceinline__ void storeA2(__nv_bfloat16* Ahi, __nv_bfloat16* Alo,
                                        int row, int cc, float f0, float f1) {
    __nv_bfloat16 h0 = __float2bfloat16(f0), h1 = __float2bfloat16(f1);
    __nv_bfloat162 hv; hv.x = h0; hv.y = h1;
    *(__nv_bfloat162*)&Ahi[row * AK + cc] = hv;
    __nv_bfloat162 lv;
    lv.x = __float2bfloat16(f0 - __bfloat162float(h0));
    lv.y = __float2bfloat16(f1 - __bfloat162float(h1));
    *(__nv_bfloat162*)&Alo[row * AK + cc] = lv;
}

__global__ __launch_bounds__(256)
void trace_mma_kernel(const float* __restrict__ Z, const float* __restrict__ V,
                      const float* __restrict__ noise,
                      const __nv_bfloat16* __restrict__ Wbhi,
                      const __nv_bfloat16* __restrict__ Wblo,
                      const __nv_bfloat16* __restrict__ WTbhi,
                      const __nv_bfloat16* __restrict__ WTblo,
                      const float* __restrict__ bp1, const float* __restrict__ wp2,
                      float* __restrict__ mind) {
    extern __shared__ __align__(16) char dsm[];
    __nv_bfloat16* Ahi = (__nv_bfloat16*)(dsm);
    __nv_bfloat16* Alo = (__nv_bfloat16*)(dsm + O_ALO);
    float* v_sm  = (float*)(dsm + O_V);
    float* xa_sm = (float*)(dsm + O_XA);
    float* va_sm = (float*)(dsm + O_VA);
    float* red_a = (float*)(dsm + O_RA);
    float* red_b = (float*)(dsm + O_RB);
    float* bc_a  = (float*)(dsm + O_BA);
    float* bc_b  = (float*)(dsm + O_BB);

    const int tid  = threadIdx.x;
    const int wid  = tid >> 5;
    const int lane = tid & 31;
    const int r    = lane >> 2;
    const int c2   = (lane & 3) * 2;
    const int wn   = wid * 32;
    const int s0   = blockIdx.x * SC;
    const float hs = 1.0f / 15.0f;
    const int wrow = tid >> 2;
    const int wcol = (tid & 3) * 8;

    float x[32], vt[32], g[32], d[32];
    float bpr[8], w2r[8];
#pragma unroll
    for (int nf = 0; nf < 4; nf++)
#pragma unroll
        for (int jl = 0; jl < 2; jl++) {
            const int col = wn + nf * 8 + c2 + jl;
            bpr[nf * 2 + jl] = bp1[col];
            w2r[nf * 2 + jl] = wp2[col];
        }

    for (int i = tid; i < SC * DD; i += 256)
        v_sm[(i >> 8) * VROW + (i & 255)] = V[(size_t)(s0 + (i >> 8)) * DD + (i & 255)];
#pragma unroll
    for (int mf = 0; mf < 2; mf++)
#pragma unroll
        for (int nf = 0; nf < 4; nf++)
#pragma unroll
            for (int jp = 0; jp < 2; jp++) {
                const int smp = mf * 16 + r + 8 * jp;
                const int cc = wn + nf * 8 + c2;
                float2 xv = *(const float2*)&Z[(size_t)(s0 + smp) * DD + cc];
                x[mf * 16 + nf * 4 + jp * 2]     = xv.x;
                x[mf * 16 + nf * 4 + jp * 2 + 1] = xv.y;
            }
    float mymin = 3.4e38f;
    __syncthreads();

#define FOR_PAIR(...)                                                          \
    _Pragma("unroll") for (int mf = 0; mf < 2; mf++)                           \
    _Pragma("unroll") for (int nf = 0; nf < 4; nf++)                           \
    _Pragma("unroll") for (int jp = 0; jp < 2; jp++) {                         \
        const int e0 = mf * 16 + nf * 4 + jp * 2;                              \
        const int row = mf * 16 + r + 8 * jp;                                  \
        const int cc = wn + nf * 8 + c2;                                       \
        const int vidx = row * VROW + cc;                                      \
        (void)e0; (void)row; (void)cc; (void)vidx;                             \
        __VA_ARGS__                                                            \
    }

    // ---- folded degenerate-wind fallback ----
    {
        float pv[4] = {0.f, 0.f, 0.f, 0.f};
        float pn[4] = {0.f, 0.f, 0.f, 0.f};
        FOR_PAIR({
            float2 vv = *(float2*)&v_sm[vidx];
            float2 nz = *(const float2*)&noise[(size_t)(s0 + row) * DD + cc];
            pv[mf * 2 + jp] += vv.x * vv.x + vv.y * vv.y;
            pn[mf * 2 + jp] += nz.x * nz.x + nz.y * nz.y;
        })
#pragma unroll
        for (int sl = 0; sl < 4; sl++) {
            pv[sl] += __shfl_xor_sync(0xffffffffu, pv[sl], 1);
            pv[sl] += __shfl_xor_sync(0xffffffffu, pv[sl], 2);
            pn[sl] += __shfl_xor_sync(0xffffffffu, pn[sl], 1);
            pn[sl] += __shfl_xor_sync(0xffffffffu, pn[sl], 2);
        }
        if ((lane & 3) == 0) {
#pragma unroll
            for (int sl = 0; sl < 4; sl++) {
                const int row = (sl >> 1) * 16 + r + 8 * (sl & 1);
                red_a[wid * 32 + row] = pv[sl];
                red_b[wid * 32 + row] = pn[sl];
            }
        }
        __syncthreads();
        if (tid < 32) {
            float sv2 = 0.f, sn2 = 0.f;
#pragma unroll
            for (int w8 = 0; w8 < 8; w8++) {
                sv2 += red_a[w8 * 32 + tid];
                sn2 += red_b[w8 * 32 + tid];
            }
            bc_a[tid] = sv2;
            bc_b[tid] = sn2;
        }
        __syncthreads();
        FOR_PAIR({
            float wnrm = sqrtf(bc_a[row] + 1e-24f);
            if (wnrm < 1e-5f) {
                float nn = sqrtf(bc_b[row] + 1e-24f);
                float2 nz = *(const float2*)&noise[(size_t)(s0 + row) * DD + cc];
                float2 vv = *(float2*)&v_sm[vidx];
                vv.x += nz.x / (nn + 1e-12f) * 1e-4f;
                vv.y += nz.y / (nn + 1e-12f) * 1e-4f;
                *(float2*)&v_sm[vidx] = vv;
            }
        })
        __syncthreads();
    }

#define MATVEC(BHI, BLO)                                                       \
    do {                                                                       \
        _Pragma("unroll") for (int e = 0; e < 32; e++) d[e] = 0.f;             \
        uint4 rh[4], rl[4];                                                    \
        _Pragma("unroll") for (int p = 0; p < 4; p++) {                        \
            rh[p] = *(const uint4*)((BHI) + (size_t)(p * 64 + wrow) * DD + wcol); \
            rl[p] = *(const uint4*)((BLO) + (size_t)(p * 64 + wrow) * DD + wcol); \
        }                                                                      \
        {                                                                      \
            __nv_bfloat16* wh = (__nv_bfloat16*)(dsm + O_WB);                  \
            __nv_bfloat16* wl = wh + 10240;                                    \
            _Pragma("unroll") for (int p = 0; p < 4; p++) {                    \
                *(uint4*)(wh + (p * 64 + wrow) * WK + wcol) = rh[p];           \
                *(uint4*)(wl + (p * 64 + wrow) * WK + wcol) = rl[p];           \
            }                                                                  \
        }                                                                      \
        _Pragma("unroll 1") for (int c = 0; c < 8; c++) {                      \
            __syncthreads();                                                   \
            if (c < 7) {                                                       \
                const int k0n = (c + 1) * 32;                                  \
                _Pragma("unroll") for (int p = 0; p < 4; p++) {                \
                    rh[p] = *(const uint4*)((BHI) + (size_t)(p * 64 + wrow) * DD + k0n + wcol); \
                    rl[p] = *(const uint4*)((BLO) + (size_t)(p * 64 + wrow) * DD + k0n + wcol); \
                }                                                              \
            }                                                                  \
            const __nv_bfloat16* wbh =                                         \
                (const __nv_bfloat16*)(dsm + O_WB + (c & 1) * 40960);          \
            const __nv_bfloat16* wbl = wbh + 10240;                            \
            const int k0 = c * 32;                                             \
            _Pragma("unroll") for (int kk = 0; kk < 32; kk += 16) {            \
                uint32_t ah[2][4], al[2][4];                                   \
                _Pragma("unroll") for (int mf = 0; mf < 2; mf++) {             \
                    const int mr = mf * 16 + r;                                \
                    ah[mf][0] = *(const uint32_t*)&Ahi[mr * AK + k0 + kk + c2]; \
                    ah[mf][1] = *(const uint32_t*)&Ahi[(mr + 8) * AK + k0 + kk + c2]; \
                    ah[mf][2] = *(const uint32_t*)&Ahi[mr * AK + k0 + kk + c2 + 8]; \
                    ah[mf][3] = *(const uint32_t*)&Ahi[(mr + 8) * AK + k0 + kk + c2 + 8]; \
                    al[mf][0] = *(const uint32_t*)&Alo[mr * AK + k0 + kk + c2]; \
                    al[mf][1] = *(const uint32_t*)&Alo[(mr + 8) * AK + k0 + kk + c2]; \
                    al[mf][2] = *(const uint32_t*)&Alo[mr * AK + k0 + kk + c2 + 8]; \
                    al[mf][3] = *(const uint32_t*)&Alo[(mr + 8) * AK + k0 + kk + c2 + 8]; \
                }                                                              \
                _Pragma("unroll") for (int nf = 0; nf < 4; nf++) {             \
                    const int nb = wn + nf * 8 + r;                            \
                    uint32_t bh[2], bl[2];                                     \
                    bh[0] = *(const uint32_t*)&wbh[nb * WK + kk + c2];         \
                    bh[1] = *(const uint32_t*)&wbh[nb * WK + kk + c2 + 8];     \
                    bl[0] = *(const uint32_t*)&wbl[nb * WK + kk + c2];         \
                    bl[1] = *(const uint32_t*)&wbl[nb * WK + kk + c2 + 8];     \
                    _Pragma("unroll") for (int mf = 0; mf < 2; mf++) {         \
                        mma_bf16(&d[mf * 16 + nf * 4], ah[mf], bh);            \
                        mma_bf16(&d[mf * 16 + nf * 4], ah[mf], bl);            \
                        mma_bf16(&d[mf * 16 + nf * 4], al[mf], bh);            \
                    }                                                          \
                }                                                              \
            }                                                                  \
            if (c < 7) {                                                       \
                __nv_bfloat16* wsh =                                           \
                    (__nv_bfloat16*)(dsm + O_WB + ((c + 1) & 1) * 40960);      \
                __nv_bfloat16* wsl = wsh + 10240;                              \
                _Pragma("unroll") for (int p = 0; p < 4; p++) {                \
                    *(uint4*)(wsh + (p * 64 + wrow) * WK + wcol) = rh[p];      \
                    *(uint4*)(wsl + (p * 64 + wrow) * WK + wcol) = rl[p];      \
                }                                                              \
            }                                                                  \
        }                                                                      \
        __syncthreads();                                                       \
    } while (0)

#define ACCEL()                                                                \
    do {                                                                       \
        __syncthreads();                                                       \
        MATVEC(WTbhi, WTblo);                                                  \
        _Pragma("unroll") for (int mf = 0; mf < 2; mf++)                       \
        _Pragma("unroll") for (int nf = 0; nf < 4; nf++)                       \
        _Pragma("unroll") for (int jp = 0; jp < 2; jp++) {                     \
            const int e0 = mf * 16 + nf * 4 + jp * 2;                          \
            float h0 = tanhf(d[e0] + bpr[nf * 2]);                             \
            float h1 = tanhf(d[e0 + 1] + bpr[nf * 2 + 1]);                     \
            float sv0 = (1.0f - h0 * h0) * w2r[nf * 2];                        \
            float sv1 = (1.0f - h1 * h1) * w2r[nf * 2 + 1];                    \
            storeA2(Ahi, Alo, mf * 16 + r + 8 * jp, wn + nf * 8 + c2, sv0, sv1); \
        }                                                                      \
        __syncthreads();                                                       \
        MATVEC(Wbhi, Wblo);                                                    \
        {                                                                      \
            float pg[4] = {0.f, 0.f, 0.f, 0.f};                                \
            float pv[4] = {0.f, 0.f, 0.f, 0.f};                                \
            _Pragma("unroll") for (int mf = 0; mf < 2; mf++)                   \
            _Pragma("unroll") for (int nf = 0; nf < 4; nf++)                   \
            _Pragma("unroll") for (int j = 0; j < 4; j++) {                    \
                const int e = mf * 16 + nf * 4 + j;                            \
                const int sl = mf * 2 + (j >> 1);                              \
                pg[sl] += d[e] * vt[e];                                        \
                pv[sl] += vt[e] * vt[e];                                       \
            }                                                                  \
            _Pragma("unroll") for (int sl = 0; sl < 4; sl++) {                 \
                pg[sl] += __shfl_xor_sync(0xffffffffu, pg[sl], 1);             \
                pg[sl] += __shfl_xor_sync(0xffffffffu, pg[sl], 2);             \
                pv[sl] += __shfl_xor_sync(0xffffffffu, pv[sl], 1);             \
                pv[sl] += __shfl_xor_sync(0xffffffffu, pv[sl], 2);             \
            }                                                                  \
            if ((lane & 3) == 0) {                                             \
                _Pragma("unroll") for (int sl = 0; sl < 4; sl++) {             \
                    const int row = (sl >> 1) * 16 + r + 8 * (sl & 1);         \
                    red_a[wid * 32 + row] = pg[sl];                            \
                    red_b[wid * 32 + row] = pv[sl];                            \
                }                                                              \
            }                                                                  \
        }                                                                      \
        __syncthreads();                                                       \
        if (tid < 32) {                                                        \
            float sg = 0.f;                                                    \
            float sv2 = 0.f;                                                   \
            _Pragma("unroll") for (int w8 = 0; w8 < 8; w8++) {                 \
                sg += red_a[w8 * 32 + tid];                                    \
                sv2 += red_b[w8 * 32 + tid];                                   \
            }                                                                  \
            bc_a[tid] = sg;                                                    \
            bc_b[tid] = sv2;                                                   \
        }                                                                      \
        __syncthreads();                                                       \
        _Pragma("unroll") for (int mf = 0; mf < 2; mf++)                       \
        _Pragma("unroll") for (int nf = 0; nf < 4; nf++)                       \
        _Pragma("unroll") for (int j = 0; j < 4; j++) {                        \
            const int e = mf * 16 + nf * 4 + j;                                \
            const int smp = mf * 16 + r + 8 * (j >> 1);                        \
            g[e] = 0.5f * bc_b[smp] * d[e] - bc_a[smp] * vt[e];                \
        }                                                                      \
    } while (0)

    for (int step = 0; step < NSTEP; step++) {
        FOR_PAIR({
            float2 vv = *(float2*)&v_sm[vidx];
            vt[e0] = vv.x; vt[e0 + 1] = vv.y;
            storeA2(Ahi, Alo, row, cc, x[e0], x[e0 + 1]);
        })
        ACCEL();
        FOR_PAIR({
            float2 t0; t0.x = vt[e0]; t0.y = vt[e0 + 1];
            *(float2*)&xa_sm[vidx] = t0;
            float2 t1; t1.x = g[e0]; t1.y = g[e0 + 1];
            *(float2*)&va_sm[vidx] = t1;
        })
        FOR_PAIR({
            storeA2(Ahi, Alo, row, cc,
                    x[e0] + 0.5f * hs * vt[e0], x[e0 + 1] + 0.5f * hs * vt[e0 + 1]);
            vt[e0]     += 0.5f * hs * g[e0];
            vt[e0 + 1] += 0.5f * hs * g[e0 + 1];
        })
        ACCEL();
        FOR_PAIR({
            float2 xv = *(float2*)&xa_sm[vidx];
            xv.x += 2.0f * vt[e0]; xv.y += 2.0f * vt[e0 + 1];
            *(float2*)&xa_sm[vidx] = xv;
            float2 av = *(float2*)&va_sm[vidx];
            av.x += 2.0f * g[e0]; av.y += 2.0f * g[e0 + 1];
            *(float2*)&va_sm[vidx] = av;
        })
        FOR_PAIR({
            storeA2(Ahi, Alo, row, cc,
                    x[e0] + 0.5f * hs * vt[e0], x[e0 + 1] + 0.5f * hs * vt[e0 + 1]);
            float2 vv = *(float2*)&v_sm[vidx];
            vt[e0]     = vv.x + 0.5f * hs * g[e0];
            vt[e0 + 1] = vv.y + 0.5f * hs * g[e0 + 1];
        })
        ACCEL();
        FOR_PAIR({
            float2 xv = *(float2*)&xa_sm[vidx];
            xv.x += 2.0f * vt[e0]; xv.y += 2.0f * vt[e0 + 1];
            *(float2*)&xa_sm[vidx] = xv;
            float2 av = *(float2*)&va_sm[vidx];
            av.x += 2.0f * g[e0]; av.y += 2.0f * g[e0 + 1];
            *(float2*)&va_sm[vidx] = av;
        })
        FOR_PAIR({
            storeA2(Ahi, Alo, row, cc,
                    x[e0] + hs * vt[e0], x[e0 + 1] + hs * vt[e0 + 1]);
            float2 vv = *(float2*)&v_sm[vidx];
            vt[e0]     = vv.x + hs * g[e0];
            vt[e0 + 1] = vv.y + hs * g[e0 + 1];
        })
        ACCEL();
        {
            float pd[4] = {0.f, 0.f, 0.f, 0.f};
            FOR_PAIR({
                float2 xav = *(float2*)&xa_sm[vidx];
                float2 vav = *(float2*)&va_sm[vidx];
                float2 vv  = *(float2*)&v_sm[vidx];
                x[e0]     += (hs / 6.0f) * (xav.x + vt[e0]);
                x[e0 + 1] += (hs / 6.0f) * (xav.y + vt[e0 + 1]);
                vv.x += (hs / 6.0f) * (vav.x + g[e0]);
                vv.y += (hs / 6.0f) * (vav.y + g[e0 + 1]);
                *(float2*)&v_sm[vidx] = vv;
                float2 zev = *(const float2*)&Z[(size_t)(NB + s0 + row) * DD + cc];
                float dd0 = x[e0] - zev.x;
                float dd1 = x[e0 + 1] - zev.y;
                pd[mf * 2 + jp] += dd0 * dd0 + dd1 * dd1;
            })
#pragma unroll
            for (int sl = 0; sl < 4; sl++) {
                pd[sl] += __shfl_xor_sync(0xffffffffu, pd[sl], 1);
                pd[sl] += __shfl_xor_sync(0xffffffffu, pd[sl], 2);
            }
            if ((lane & 3) == 0) {
#pragma unroll
                for (int sl = 0; sl < 4; sl++) {
                    const int row = (sl >> 1) * 16 + r + 8 * (sl & 1);
                    red_a[wid * 32 + row] = pd[sl];
                }
            }
            __syncthreads();
            if (tid < 32) {
                float tot = 0.f;
#pragma unroll
                for (int w8 = 0; w8 < 8; w8++) tot += red_a[w8 * 32 + tid];
                mymin = fminf(mymin, tot);
            }
            __syncthreads();
        }
    }

    if (tid < 32) mind[s0 + tid] = mymin;
#undef FOR_PAIR
#undef ACCEL
#undef MATVEC
}

// ---------------------------------------------------------------------------
__global__ void reduce_kernel(const float* __restrict__ mind, float* __restrict__ out) {
    __shared__ float sm[1024];
    const int t = threadIdx.x;
    float a = mind[t] + mind[t + 1024] + mind[t + 2048] + mind[t + 3072];
    sm[t] = a;
    __syncthreads();
    for (int off = 512; off > 0; off >>= 1) {
        if (t < off) sm[t] += sm[t + off];
        __syncthreads();
    }
    if (t == 0) out[0] = sm[0] * (1.0f / (float)NB);
}

// ---------------------------------------------------------------------------
// Launch — trace is launch index 5 (ncu -s 5 -c 1 captures it)
// ---------------------------------------------------------------------------
extern "C" void kernel_launch(void* const* d_in, const int* in_sizes, int n_in,
                              void* d_out, int out_size) {
    const float* x_start = (const float*)d_in[0];
    const float* x_end   = (const float*)d_in[1];
    const float* noise   = (const float*)d_in[2];
    const float* W1  = (const float*)d_in[3];
    const float* b1  = (const float*)d_in[4];
    const float* W2  = (const float*)d_in[5];
    const float* b2  = (const float*)d_in[6];
    const float* Ww1 = (const float*)d_in[7];
    const float* bw1 = (const float*)d_in[8];
    const float* Ww2 = (const float*)d_in[9];
    const float* bw2 = (const float*)d_in[10];
    const float* Wp1 = (const float*)d_in[11];
    const float* bp1 = (const float*)d_in[12];
    const float* wp2 = (const float*)d_in[13];

    float *Zb, *Vb, *Md;
    cudaGetSymbolAddress((void**)&Zb, g_Z);
    cudaGetSymbolAddress((void**)&Vb, g_V);
    cudaGetSymbolAddress((void**)&Md, g_mind);
    __nv_bfloat16 *Xhi, *Xlo, *Hhi, *Hlo, *Zshi, *Zslo, *HWhi, *HWlo;
    __nv_bfloat16 *W1h, *W1l, *W2h, *W2l, *Ww1h, *Ww1l, *Ww2h, *Ww2l;
    __nv_bfloat16 *Wph, *Wpl, *WTh, *WTl;
    cudaGetSymbolAddress((void**)&Xhi,  g_Xhi);
    cudaGetSymbolAddress((void**)&Xlo,  g_Xlo);
    cudaGetSymbolAddress((void**)&Hhi,  g_Hhi);
    cudaGetSymbolAddress((void**)&Hlo,  g_Hlo);
    cudaGetSymbolAddress((void**)&Zshi, g_Zshi);
    cudaGetSymbolAddress((void**)&Zslo, g_Zslo);
    cudaGetSymbolAddress((void**)&HWhi, g_HWhi);
    cudaGetSymbolAddress((void**)&HWlo, g_HWlo);
    cudaGetSymbolAddress((void**)&W1h,  g_W1Thi);
    cudaGetSymbolAddress((void**)&W1l,  g_W1Tlo);
    cudaGetSymbolAddress((void**)&W2h,  g_W2Thi);
    cudaGetSymbolAddress((void**)&W2l,  g_W2Tlo);
    cudaGetSymbolAddress((void**)&Ww1h, g_Ww1Thi);
    cudaGetSymbolAddress((void**)&Ww1l, g_Ww1Tlo);
    cudaGetSymbolAddress((void**)&Ww2h, g_Ww2Thi);
    cudaGetSymbolAddress((void**)&Ww2l, g_Ww2Tlo);
    cudaGetSymbolAddress((void**)&Wph,  g_Wbhi);
    cudaGetSymbolAddress((void**)&Wpl,  g_Wblo);
    cudaGetSymbolAddress((void**)&WTh,  g_WTbhi);
    cudaGetSymbolAddress((void**)&WTl,  g_WTblo);

    cudaFuncSetAttribute(trace_mma_kernel,
                         cudaFuncAttributeMaxDynamicSharedMemorySize, TR_SMEM_BYTES);

    const int nconv = XB + TB_W1 + TB_W2 + 3 * TB_WW;
    // 0: all conversions
    conv_all_kernel<<<nconv, 256>>>(x_start, x_end, W1, W2, Ww1, Ww2, Wp1,
                                    Xhi, Xlo, W1h, W1l, W2h, W2l,
                                    Ww1h, Ww1l, Ww2h, Ww2l, Wph, Wpl, WTh, WTl);
    // 1: enc1  Hb = tanh(X @ W1 + b1)  (bf16 hi/lo out)
    gemm_mma_kernel<1><<<dim3(HH / 128, 2 * NB / 128), 256>>>(
        Xhi, Xlo, W1h, W1l, b1, nullptr, Hhi, Hlo, 2 * NB, HH, DIN);
    // 2: enc2  Z = Hb @ W2 + b2  (fp32 full; z_s rows also bf16 hi/lo)
    gemm_mma_kernel<0><<<dim3(DD / 128, 2 * NB / 128), 256>>>(
        Hhi, Hlo, W2h, W2l, b2, Zb, Zshi, Zslo, NB, DD, HH);
    // 3: wind1  HW = tanh(z_s @ Ww1 + bw1)  (bf16 hi/lo out)
    gemm_mma_kernel<1><<<dim3(DD / 128, NB / 128), 256>>>(
        Zshi, Zslo, Ww1h, Ww1l, bw1, nullptr, HWhi, HWlo, NB, DD, DD);
    // 4: wind2  V = HW @ Ww2 + bw2  (fp32 out)
    gemm_mma_kernel<0><<<dim3(DD / 128, NB / 128), 256>>>(
        HWhi, HWlo, Ww2h, Ww2l, bw2, Vb, nullptr, nullptr, 0, DD, DD);
    // 5: trace (fallback folded in)  <-- ncu capture target
    trace_mma_kernel<<<NB / SC, 256, TR_SMEM_BYTES>>>(
        Zb, Vb, noise, Wph, Wpl, WTh, WTl, bp1, wp2, Md);
    // 6: mean
    reduce_kernel<<<1, 1024>>>(Md, (float*)d_out);
}

// round 16
// speedup vs baseline: 1.0962x; 1.0350x over previous
#include <cuda_runtime.h>
#include <cuda_bf16.h>
#include <cstdint>

// ---------------------------------------------------------------------------
// Problem constants
// ---------------------------------------------------------------------------
#define NB    4096
#define DIN   2048
#define HH    1024
#define DD    256
#define NSTEP 15
#define SC    32     // samples per trace CTA

// ---------------------------------------------------------------------------
// Scratch (device globals; no allocation allowed)
// ---------------------------------------------------------------------------
__device__ float g_Z   [2 * NB * DD];    // fp32 Z (z_s | z_e)
__device__ float g_V   [NB * DD];
__device__ float g_mind[NB];
__device__ __nv_bfloat16 g_Xhi [2 * NB * DIN];
__device__ __nv_bfloat16 g_Xlo [2 * NB * DIN];
__device__ __nv_bfloat16 g_Hhi [2 * NB * HH];
__device__ __nv_bfloat16 g_Hlo [2 * NB * HH];
__device__ __nv_bfloat16 g_Zshi[NB * DD];
__device__ __nv_bfloat16 g_Zslo[NB * DD];
__device__ __nv_bfloat16 g_HWhi[NB * DD];
__device__ __nv_bfloat16 g_HWlo[NB * DD];
__device__ __nv_bfloat16 g_W1Thi[HH * DIN];
__device__ __nv_bfloat16 g_W1Tlo[HH * DIN];
__device__ __nv_bfloat16 g_W2Thi[DD * HH];
__device__ __nv_bfloat16 g_W2Tlo[DD * HH];
__device__ __nv_bfloat16 g_Ww1Thi[DD * DD];
__device__ __nv_bfloat16 g_Ww1Tlo[DD * DD];
__device__ __nv_bfloat16 g_Ww2Thi[DD * DD];
__device__ __nv_bfloat16 g_Ww2Tlo[DD * DD];
__device__ __nv_bfloat16 g_Wbhi [DD * DD];
__device__ __nv_bfloat16 g_Wblo [DD * DD];
__device__ __nv_bfloat16 g_WTbhi[DD * DD];
__device__ __nv_bfloat16 g_WTblo[DD * DD];

// ---------------------------------------------------------------------------
// Warp-level bf16 MMA
// ---------------------------------------------------------------------------
__device__ __forceinline__ void mma_bf16(float* d, const uint32_t* a,
                                         const uint32_t* b) {
    asm volatile(
        "mma.sync.aligned.m16n8k16.row.col.f32.bf16.bf16.f32 "
        "{%0,%1,%2,%3}, {%4,%5,%6,%7}, {%8,%9}, {%0,%1,%2,%3};"
        : "+f"(d[0]), "+f"(d[1]), "+f"(d[2]), "+f"(d[3])
        : "r"(a[0]), "r"(a[1]), "r"(a[2]), "r"(a[3]), "r"(b[0]), "r"(b[1]));
}

// cp.async helpers (sm_80-baseline PTX -> valid on compute_103)
__device__ __forceinline__ void cp_async16(void* sptr, const void* gptr) {
    uint32_t sa = (uint32_t)__cvta_generic_to_shared(sptr);
    asm volatile("cp.async.ca.shared.global [%0], [%1], 16;"
                 :: "r"(sa), "l"(gptr));
}
#define CP_COMMIT() asm volatile("cp.async.commit_group;" ::: "memory")
#define CP_WAIT(n)  asm volatile("cp.async.wait_group %0;" :: "n"(n) : "memory")

// ---------------------------------------------------------------------------
// Mega conversion kernel (ONE launch). Sections as R15.
// ---------------------------------------------------------------------------
#define XB    (2 * NB * DIN / (256 * 4))        // 16384
#define TB_W1 2048
#define TB_W2 256
#define TB_WW 64

__device__ __forceinline__ void split_bf16(float v, __nv_bfloat16& h, __nv_bfloat16& l) {
    h = __float2bfloat16(v);
    l = __float2bfloat16(v - __bfloat162float(h));
}

__device__ void conv_tileT(const float* __restrict__ in,
                           __nv_bfloat16* __restrict__ hi,
                           __nv_bfloat16* __restrict__ lo,
                           int K, int N, int tileIdx) {
    __shared__ float tile[32][33];
    const int ntiles_n = N / 32;
    const int k0 = (tileIdx / ntiles_n) * 32;
    const int n0 = (tileIdx % ntiles_n) * 32;
    const int tx = threadIdx.x & 31;
    const int ty4 = (threadIdx.x >> 5) * 4;
#pragma unroll
    for (int i = 0; i < 4; i++)
        tile[ty4 + i][tx] = in[(size_t)(k0 + ty4 + i) * N + n0 + tx];
    __syncthreads();
#pragma unroll
    for (int i = 0; i < 4; i++) {
        float v = tile[tx][ty4 + i];
        __nv_bfloat16 h, l; split_bf16(v, h, l);
        hi[(size_t)(n0 + ty4 + i) * K + k0 + tx] = h;
        lo[(size_t)(n0 + ty4 + i) * K + k0 + tx] = l;
    }
}

__global__ __launch_bounds__(256)
void conv_all_kernel(const float* __restrict__ xs, const float* __restrict__ xe,
                     const float* __restrict__ W1, const float* __restrict__ W2,
                     const float* __restrict__ Ww1, const float* __restrict__ Ww2,
                     const float* __restrict__ Wp1,
                     __nv_bfloat16* __restrict__ Xhi, __nv_bfloat16* __restrict__ Xlo,
                     __nv_bfloat16* __restrict__ W1h, __nv_bfloat16* __restrict__ W1l,
                     __nv_bfloat16* __restrict__ W2h, __nv_bfloat16* __restrict__ W2l,
                     __nv_bfloat16* __restrict__ Ww1h, __nv_bfloat16* __restrict__ Ww1l,
                     __nv_bfloat16* __restrict__ Ww2h, __nv_bfloat16* __restrict__ Ww2l,
                     __nv_bfloat16* __restrict__ Wph, __nv_bfloat16* __restrict__ Wpl,
                     __nv_bfloat16* __restrict__ WTh, __nv_bfloat16* __restrict__ WTl) {
    int b = blockIdx.x;
    if (b < XB) {
        const size_t i4 = ((size_t)b * 256 + threadIdx.x) * 4;
        const size_t half = (size_t)NB * DIN;
        const float* src = (i4 < half) ? xs + i4 : xe + (i4 - half);
        float4 v = *(const float4*)src;
        float vv[4] = {v.x, v.y, v.z, v.w};
        __nv_bfloat16 h[4], l[4];
#pragma unroll
        for (int j = 0; j < 4; j++) split_bf16(vv[j], h[j], l[j]);
        *(uint2*)(Xhi + i4) = *(uint2*)h;
        *(uint2*)(Xlo + i4) = *(uint2*)l;
        return;
    }
    b -= XB;
    if (b < TB_W1) { conv_tileT(W1, W1h, W1l, DIN, HH, b); return; }
    b -= TB_W1;
    if (b < TB_W2) { conv_tileT(W2, W2h, W2l, HH, DD, b); return; }
    b -= TB_W2;
    if (b < TB_WW) { conv_tileT(Ww1, Ww1h, Ww1l, DD, DD, b); return; }
    b -= TB_WW;
    if (b < TB_WW) { conv_tileT(Ww2, Ww2h, Ww2l, DD, DD, b); return; }
    b -= TB_WW;
    {
        __shared__ float tile[32][33];
        const int i0 = (b / 8) * 32;
        const int j0 = (b % 8) * 32;
        const int tx = threadIdx.x & 31;
        const int ty4 = (threadIdx.x >> 5) * 4;
#pragma unroll
        for (int i = 0; i < 4; i++) {
            float w = Wp1[(size_t)(i0 + ty4 + i) * DD + j0 + tx];
            tile[ty4 + i][tx] = w;
            __nv_bfloat16 h, l; split_bf16(w, h, l);
            Wph[(size_t)(i0 + ty4 + i) * DD + j0 + tx] = h;
            Wpl[(size_t)(i0 + ty4 + i) * DD + j0 + tx] = l;
        }
        __syncthreads();
#pragma unroll
        for (int i = 0; i < 4; i++) {
            float w = tile[tx][ty4 + i];
            __nv_bfloat16 h, l; split_bf16(w, h, l);
            WTh[(size_t)(j0 + ty4 + i) * DD + i0 + tx] = h;
            WTl[(size_t)(j0 + ty4 + i) * DD + i0 + tx] = l;
        }
    }
}

// ---------------------------------------------------------------------------
// Unified HMMA GEMM (bf16x3) with cp.async 2-stage pipeline.
// Chunk-32 tiles (TSTR=40), double-buffered dynamic smem (2 x 40960 B).
// ---------------------------------------------------------------------------
#define TSTR 40
#define GM_BUF   (4 * 128 * TSTR)            // bf16 elems per stage (A/Al/B/Bl)
#define GM_SMEM  (2 * GM_BUF * 2)            // bytes = 81920

// issue cp.async loads of one chunk into stage buffer s (4 tiles)
__device__ __forceinline__ void gm_issue_chunk(
    __nv_bfloat16* stage, const __nv_bfloat16* __restrict__ Ahi,
    const __nv_bfloat16* __restrict__ Alo,
    const __nv_bfloat16* __restrict__ Bhi,
    const __nv_bfloat16* __restrict__ Blo,
    int m0, int n0, int k0, int K, int tid) {
    __nv_bfloat16* Ah = stage;
    __nv_bfloat16* Al = stage + 128 * TSTR;
    __nv_bfloat16* Bh = stage + 2 * 128 * TSTR;
    __nv_bfloat16* Bl = stage + 3 * 128 * TSTR;
#pragma unroll
    for (int i = 0; i < 2; i++) {
        const int cid = tid + i * 256;
        const int r = cid >> 2;
        const int c = (cid & 3) * 8;
        cp_async16(Ah + r * TSTR + c, Ahi + (size_t)(m0 + r) * K + k0 + c);
        cp_async16(Al + r * TSTR + c, Alo + (size_t)(m0 + r) * K + k0 + c);
        cp_async16(Bh + r * TSTR + c, Bhi + (size_t)(n0 + r) * K + k0 + c);
        cp_async16(Bl + r * TSTR + c, Blo + (size_t)(n0 + r) * K + k0 + c);
    }
}

template <int ACT>
__global__ __launch_bounds__(256, 2)
void gemm_mma_kernel(const __nv_bfloat16* __restrict__ Ahi,
                     const __nv_bfloat16* __restrict__ Alo,
                     const __nv_bfloat16* __restrict__ Bhi,
                     const __nv_bfloat16* __restrict__ Blo,
                     const float* __restrict__ bias,
                     float* __restrict__ Cf,
                     __nv_bfloat16* __restrict__ Chi,
                     __nv_bfloat16* __restrict__ Clo,
                     int bfLimit, int N, int K) {
    extern __shared__ __align__(16) __nv_bfloat16 smg[];

    const int tid  = threadIdx.x;
    const int wid  = tid >> 5;
    const int lane = tid & 31;
    const int n0   = blockIdx.x * 128;
    const int m0   = blockIdx.y * 128;
    const int wm   = (wid & 3) * 32;
    const int wn   = (wid >> 2) * 64;
    const int r    = lane >> 2;
    const int c2   = (lane & 3) * 2;

    float d[2][8][4];
#pragma unroll
    for (int mf = 0; mf < 2; mf++)
#pragma unroll
        for (int nf = 0; nf < 8; nf++)
#pragma unroll
            for (int j = 0; j < 4; j++) d[mf][nf][j] = 0.0f;

    const int NC = K / 32;
    // prologue: stage 0
    gm_issue_chunk(smg, Ahi, Alo, Bhi, Blo, m0, n0, 0, K, tid);
    CP_COMMIT();

    for (int ch = 0; ch < NC; ch++) {
        const bool has_next = (ch + 1 < NC);
        if (has_next) {
            gm_issue_chunk(smg + ((ch + 1) & 1) * GM_BUF,
                           Ahi, Alo, Bhi, Blo, m0, n0, (ch + 1) * 32, K, tid);
            CP_COMMIT();
            CP_WAIT(1);
        } else {
            CP_WAIT(0);
        }
        __syncthreads();

        const __nv_bfloat16* st = smg + (ch & 1) * GM_BUF;
        const __nv_bfloat16* Ah = st;
        const __nv_bfloat16* Al = st + 128 * TSTR;
        const __nv_bfloat16* Bh = st + 2 * 128 * TSTR;
        const __nv_bfloat16* Bl = st + 3 * 128 * TSTR;

#pragma unroll
        for (int kk = 0; kk < 32; kk += 16) {
            uint32_t ah[2][4], al[2][4];
#pragma unroll
            for (int mf = 0; mf < 2; mf++) {
                const int mb = wm + mf * 16;
                ah[mf][0] = *(const uint32_t*)&Ah[(mb + r) * TSTR + kk + c2];
                ah[mf][1] = *(const uint32_t*)&Ah[(mb + r + 8) * TSTR + kk + c2];
                ah[mf][2] = *(const uint32_t*)&Ah[(mb + r) * TSTR + kk + c2 + 8];
                ah[mf][3] = *(const uint32_t*)&Ah[(mb + r + 8) * TSTR + kk + c2 + 8];
                al[mf][0] = *(const uint32_t*)&Al[(mb + r) * TSTR + kk + c2];
                al[mf][1] = *(const uint32_t*)&Al[(mb + r + 8) * TSTR + kk + c2];
                al[mf][2] = *(const uint32_t*)&Al[(mb + r) * TSTR + kk + c2 + 8];
                al[mf][3] = *(const uint32_t*)&Al[(mb + r + 8) * TSTR + kk + c2 + 8];
            }
#pragma unroll
            for (int nf = 0; nf < 8; nf++) {
                const int nb = wn + nf * 8 + r;
                uint32_t bh[2], bl[2];
                bh[0] = *(const uint32_t*)&Bh[nb * TSTR + kk + c2];
                bh[1] = *(const uint32_t*)&Bh[nb * TSTR + kk + c2 + 8];
                bl[0] = *(const uint32_t*)&Bl[nb * TSTR + kk + c2];
                bl[1] = *(const uint32_t*)&Bl[nb * TSTR + kk + c2 + 8];
#pragma unroll
                for (int mf = 0; mf < 2; mf++) {
                    mma_bf16(d[mf][nf], ah[mf], bh);
                    mma_bf16(d[mf][nf], ah[mf], bl);
                    mma_bf16(d[mf][nf], al[mf], bh);
                }
            }
        }
        __syncthreads();   // compute done before this buffer is refilled (iter ch+1)
    }

    // fused epilogue
#pragma unroll
    for (int mf = 0; mf < 2; mf++) {
        const int row = m0 + wm + mf * 16 + r;
#pragma unroll
        for (int nf = 0; nf < 8; nf++) {
            const int col = n0 + wn + nf * 8 + c2;
            const float bb0 = bias[col], bb1 = bias[col + 1];
            float v0 = d[mf][nf][0] + bb0;
            float v1 = d[mf][nf][1] + bb1;
            float v2 = d[mf][nf][2] + bb0;
            float v3 = d[mf][nf][3] + bb1;
            if (ACT) { v0 = tanhf(v0); v1 = tanhf(v1); v2 = tanhf(v2); v3 = tanhf(v3); }
            if (Cf) {
                float2 p0; p0.x = v0; p0.y = v1;
                float2 p1; p1.x = v2; p1.y = v3;
                *(float2*)&Cf[(size_t)row * N + col] = p0;
                *(float2*)&Cf[(size_t)(row + 8) * N + col] = p1;
            }
            if (Chi) {
                if (row < bfLimit) {
                    __nv_bfloat162 hv, lv;
                    split_bf16(v0, hv.x, lv.x);
                    split_bf16(v1, hv.y, lv.y);
                    *(__nv_bfloat162*)&Chi[(size_t)row * N + col] = hv;
                    *(__nv_bfloat162*)&Clo[(size_t)row * N + col] = lv;
                }
                if (row + 8 < bfLimit) {
                    __nv_bfloat162 hv, lv;
                    split_bf16(v2, hv.x, lv.x);
                    split_bf16(v3, hv.y, lv.y);
                    *(__nv_bfloat162*)&Chi[(size_t)(row + 8) * N + col] = hv;
                    *(__nv_bfloat162*)&Clo[(size_t)(row + 8) * N + col] = lv;
                }
            }
        }
    }
}

// ---------------------------------------------------------------------------
// Trace kernel v6 (R15 exact, incl. folded fallback).
// ---------------------------------------------------------------------------
#define AK   264
#define WK   40
#define VROW 260
#define O_ALO 16896
#define O_WB  33792
#define O_V   115712
#define O_XA  148992
#define O_VA  182272
#define O_RA  215552
#define O_RB  216576
#define O_BA  217600
#define O_BB  217728
#define TR_SMEM_BYTES 217856

__device__ __forceinline__ void storeA2(__nv_bfloat16* Ahi, __nv_bfloat16* Alo,
                                        int row, int cc, float f0, float f1) {
    __nv_bfloat16 h0 = __float2bfloat16(f0), h1 = __float2bfloat16(f1);
    __nv_bfloat162 hv; hv.x = h0; hv.y = h1;
    *(__nv_bfloat162*)&Ahi[row * AK + cc] = hv;
    __nv_bfloat162 lv;
    lv.x = __float2bfloat16(f0 - __bfloat162float(h0));
    lv.y = __float2bfloat16(f1 - __bfloat162float(h1));
    *(__nv_bfloat162*)&Alo[row * AK + cc] = lv;
}

__global__ __launch_bounds__(256)
void trace_mma_kernel(const float* __restrict__ Z, const float* __restrict__ V,
                      const float* __restrict__ noise,
                      const __nv_bfloat16* __restrict__ Wbhi,
                      const __nv_bfloat16* __restrict__ Wblo,
                      const __nv_bfloat16* __restrict__ WTbhi,
                      const __nv_bfloat16* __restrict__ WTblo,
                      const float* __restrict__ bp1, const float* __restrict__ wp2,
                      float* __restrict__ mind) {
    extern __shared__ __align__(16) char dsm[];
    __nv_bfloat16* Ahi = (__nv_bfloat16*)(dsm);
    __nv_bfloat16* Alo = (__nv_bfloat16*)(dsm + O_ALO);
    float* v_sm  = (float*)(dsm + O_V);
    float* xa_sm = (float*)(dsm + O_XA);
    float* va_sm = (float*)(dsm + O_VA);
    float* red_a = (float*)(dsm + O_RA);
    float* red_b = (float*)(dsm + O_RB);
    float* bc_a  = (float*)(dsm + O_BA);
    float* bc_b  = (float*)(dsm + O_BB);

    const int tid  = threadIdx.x;
    const int wid  = tid >> 5;
    const int lane = tid & 31;
    const int r    = lane >> 2;
    const int c2   = (lane & 3) * 2;
    const int wn   = wid * 32;
    const int s0   = blockIdx.x * SC;
    const float hs = 1.0f / 15.0f;
    const int wrow = tid >> 2;
    const int wcol = (tid & 3) * 8;

    float x[32], vt[32], g[32], d[32];
    float bpr[8], w2r[8];
#pragma unroll
    for (int nf = 0; nf < 4; nf++)
#pragma unroll
        for (int jl = 0; jl < 2; jl++) {
            const int col = wn + nf * 8 + c2 + jl;
            bpr[nf * 2 + jl] = bp1[col];
            w2r[nf * 2 + jl] = wp2[col];
        }

    for (int i = tid; i < SC * DD; i += 256)
        v_sm[(i >> 8) * VROW + (i & 255)] = V[(size_t)(s0 + (i >> 8)) * DD + (i & 255)];
#pragma unroll
    for (int mf = 0; mf < 2; mf++)
#pragma unroll
        for (int nf = 0; nf < 4; nf++)
#pragma unroll
            for (int jp = 0; jp < 2; jp++) {
                const int smp = mf * 16 + r + 8 * jp;
                const int cc = wn + nf * 8 + c2;
                float2 xv = *(const float2*)&Z[(size_t)(s0 + smp) * DD + cc];
                x[mf * 16 + nf * 4 + jp * 2]     = xv.x;
                x[mf * 16 + nf * 4 + jp * 2 + 1] = xv.y;
            }
    float mymin = 3.4e38f;
    __syncthreads();

#define FOR_PAIR(...)                                                          \
    _Pragma("unroll") for (int mf = 0; mf < 2; mf++)                           \
    _Pragma("unroll") for (int nf = 0; nf < 4; nf++)                           \
    _Pragma("unroll") for (int jp = 0; jp < 2; jp++) {                         \
        const int e0 = mf * 16 + nf * 4 + jp * 2;                              \
        const int row = mf * 16 + r + 8 * jp;                                  \
        const int cc = wn + nf * 8 + c2;                                       \
        const int vidx = row * VROW + cc;                                      \
        (void)e0; (void)row; (void)cc; (void)vidx;                             \
        __VA_ARGS__                                                            \
    }

    // ---- folded degenerate-wind fallback ----
    {
        float pv[4] = {0.f, 0.f, 0.f, 0.f};
        float pn[4] = {0.f, 0.f, 0.f, 0.f};
        FOR_PAIR({
            float2 vv = *(float2*)&v_sm[vidx];
            float2 nz = *(const float2*)&noise[(size_t)(s0 + row) * DD + cc];
            pv[mf * 2 + jp] += vv.x * vv.x + vv.y * vv.y;
            pn[mf * 2 + jp] += nz.x * nz.x + nz.y * nz.y;
        })
#pragma unroll
        for (int sl = 0; sl < 4; sl++) {
            pv[sl] += __shfl_xor_sync(0xffffffffu, pv[sl], 1);
            pv[sl] += __shfl_xor_sync(0xffffffffu, pv[sl], 2);
            pn[sl] += __shfl_xor_sync(0xffffffffu, pn[sl], 1);
            pn[sl] += __shfl_xor_sync(0xffffffffu, pn[sl], 2);
        }
        if ((lane & 3) == 0) {
#pragma unroll
            for (int sl = 0; sl < 4; sl++) {
                const int row = (sl >> 1) * 16 + r + 8 * (sl & 1);
                red_a[wid * 32 + row] = pv[sl];
                red_b[wid * 32 + row] = pn[sl];
            }
        }
        __syncthreads();
        if (tid < 32) {
            float sv2 = 0.f, sn2 = 0.f;
#pragma unroll
            for (int w8 = 0; w8 < 8; w8++) {
                sv2 += red_a[w8 * 32 + tid];
                sn2 += red_b[w8 * 32 + tid];
            }
            bc_a[tid] = sv2;
            bc_b[tid] = sn2;
        }
        __syncthreads();
        FOR_PAIR({
            float wnrm = sqrtf(bc_a[row] + 1e-24f);
            if (wnrm < 1e-5f) {
                float nn = sqrtf(bc_b[row] + 1e-24f);
                float2 nz = *(const float2*)&noise[(size_t)(s0 + row) * DD + cc];
                float2 vv = *(float2*)&v_sm[vidx];
                vv.x += nz.x / (nn + 1e-12f) * 1e-4f;
                vv.y += nz.y / (nn + 1e-12f) * 1e-4f;
                *(float2*)&v_sm[vidx] = vv;
            }
        })
        __syncthreads();
    }

#define MATVEC(BHI, BLO)                                                       \
    do {                                                                       \
        _Pragma("unroll") for (int e = 0; e < 32; e++) d[e] = 0.f;             \
        uint4 rh[4], rl[4];                                                    \
        _Pragma("unroll") for (int p = 0; p < 4; p++) {                        \
            rh[p] = *(const uint4*)((BHI) + (size_t)(p * 64 + wrow) * DD + wcol); \
            rl[p] = *(const uint4*)((BLO) + (size_t)(p * 64 + wrow) * DD + wcol); \
        }                                                                      \
        {                                                                      \
            __nv_bfloat16* wh = (__nv_bfloat16*)(dsm + O_WB);                  \
            __nv_bfloat16* wl = wh + 10240;                                    \
            _Pragma("unroll") for (int p = 0; p < 4; p++) {                    \
                *(uint4*)(wh + (p * 64 + wrow) * WK + wcol) = rh[p];           \
                *(uint4*)(wl + (p * 64 + wrow) * WK + wcol) = rl[p];           \
            }                                                                  \
        }                                                                      \
        _Pragma("unroll 1") for (int c = 0; c < 8; c++) {                      \
            __syncthreads();                                                   \
            if (c < 7) {                                                       \
                const int k0n = (c + 1) * 32;                                  \
                _Pragma("unroll") for (int p = 0; p < 4; p++) {                \
                    rh[p] = *(const uint4*)((BHI) + (size_t)(p * 64 + wrow) * DD + k0n + wcol); \
                    rl[p] = *(const uint4*)((BLO) + (size_t)(p * 64 + wrow) * DD + k0n + wcol); \
                }                                                              \
            }                                                                  \
            const __nv_bfloat16* wbh =                                         \
                (const __nv_bfloat16*)(dsm + O_WB + (c & 1) * 40960);          \
            const __nv_bfloat16* wbl = wbh + 10240;                            \
            const int k0 = c * 32;                                             \
            _Pragma("unroll") for (int kk = 0; kk < 32; kk += 16) {            \
                uint32_t ah[2][4], al[2][4];                                   \
                _Pragma("unroll") for (int mf = 0; mf < 2; mf++) {             \
                    const int mr = mf * 16 + r;                                \
                    ah[mf][0] = *(const uint32_t*)&Ahi[mr * AK + k0 + kk + c2]; \
                    ah[mf][1] = *(const uint32_t*)&Ahi[(mr + 8) * AK + k0 + kk + c2]; \
                    ah[mf][2] = *(const uint32_t*)&Ahi[mr * AK + k0 + kk + c2 + 8]; \
                    ah[mf][3] = *(const uint32_t*)&Ahi[(mr + 8) * AK + k0 + kk + c2 + 8]; \
                    al[mf][0] = *(const uint32_t*)&Alo[mr * AK + k0 + kk + c2]; \
                    al[mf][1] = *(const uint32_t*)&Alo[(mr + 8) * AK + k0 + kk + c2]; \
                    al[mf][2] = *(const uint32_t*)&Alo[mr * AK + k0 + kk + c2 + 8]; \
                    al[mf][3] = *(const uint32_t*)&Alo[(mr + 8) * AK + k0 + kk + c2 + 8]; \
                }                                                              \
                _Pragma("unroll") for (int nf = 0; nf < 4; nf++) {             \
                    const int nb = wn + nf * 8 + r;                            \
                    uint32_t bh[2], bl[2];                                     \
                    bh[0] = *(const uint32_t*)&wbh[nb * WK + kk + c2];         \
                    bh[1] = *(const uint32_t*)&wbh[nb * WK + kk + c2 + 8];     \
                    bl[0] = *(const uint32_t*)&wbl[nb * WK + kk + c2];         \
                    bl[1] = *(const uint32_t*)&wbl[nb * WK + kk + c2 + 8];     \
                    _Pragma("unroll") for (int mf = 0; mf < 2; mf++) {         \
                        mma_bf16(&d[mf * 16 + nf * 4], ah[mf], bh);            \
                        mma_bf16(&d[mf * 16 + nf * 4], ah[mf], bl);            \
                        mma_bf16(&d[mf * 16 + nf * 4], al[mf], bh);            \
                    }                                                          \
                }                                                              \
            }                                                                  \
            if (c < 7) {                                                       \
                __nv_bfloat16* wsh =                                           \
                    (__nv_bfloat16*)(dsm + O_WB + ((c + 1) & 1) * 40960);      \
                __nv_bfloat16* wsl = wsh + 10240;                              \
                _Pragma("unroll") for (int p = 0; p < 4; p++) {                \
                    *(uint4*)(wsh + (p * 64 + wrow) * WK + wcol) = rh[p];      \
                    *(uint4*)(wsl + (p * 64 + wrow) * WK + wcol) = rl[p];      \
                }                                                              \
            }                                                                  \
        }                                                                      \
        __syncthreads();                                                       \
    } while (0)

#define ACCEL()                                                                \
    do {                                                                       \
        __syncthreads();                                                       \
        MATVEC(WTbhi, WTblo);                                                  \
        _Pragma("unroll") for (int mf = 0; mf < 2; mf++)                       \
        _Pragma("unroll") for (int nf = 0; nf < 4; nf++)                       \
        _Pragma("unroll") for (int jp = 0; jp < 2; jp++) {                     \
            const int e0 = mf * 16 + nf * 4 + jp * 2;                          \
            float h0 = tanhf(d[e0] + bpr[nf * 2]);                             \
            float h1 = tanhf(d[e0 + 1] + bpr[nf * 2 + 1]);                     \
            float sv0 = (1.0f - h0 * h0) * w2r[nf * 2];                        \
            float sv1 = (1.0f - h1 * h1) * w2r[nf * 2 + 1];                    \
            storeA2(Ahi, Alo, mf * 16 + r + 8 * jp, wn + nf * 8 + c2, sv0, sv1); \
        }                                                                      \
        __syncthreads();                                                       \
        MATVEC(Wbhi, Wblo);                                                    \
        {                                                                      \
            float pg[4] = {0.f, 0.f, 0.f, 0.f};                                \
            float pv[4] = {0.f, 0.f, 0.f, 0.f};                                \
            _Pragma("unroll") for (int mf = 0; mf < 2; mf++)                   \
            _Pragma("unroll") for (int nf = 0; nf < 4; nf++)                   \
            _Pragma("unroll") for (int j = 0; j < 4; j++) {                    \
                const int e = mf * 16 + nf * 4 + j;                            \
                const int sl = mf * 2 + (j >> 1);                              \
                pg[sl] += d[e] * vt[e];                                        \
                pv[sl] += vt[e] * vt[e];                                       \
            }                                                                  \
            _Pragma("unroll") for (int sl = 0; sl < 4; sl++) {                 \
                pg[sl] += __shfl_xor_sync(0xffffffffu, pg[sl], 1);             \
                pg[sl] += __shfl_xor_sync(0xffffffffu, pg[sl], 2);             \
                pv[sl] += __shfl_xor_sync(0xffffffffu, pv[sl], 1);             \
                pv[sl] += __shfl_xor_sync(0xffffffffu, pv[sl], 2);             \
            }                                                                  \
            if ((lane & 3) == 0) {                                             \
                _Pragma("unroll") for (int sl = 0; sl < 4; sl++) {             \
                    const int row = (sl >> 1) * 16 + r + 8 * (sl & 1);         \
                    red_a[wid * 32 + row] = pg[sl];                            \
                    red_b[wid * 32 + row] = pv[sl];                            \
                }                                                              \
            }                                                                  \
        }                                                                      \
        __syncthreads();                                                       \
        if (tid < 32) {                                                        \
            float sg = 0.f;                                                    \
            float sv2 = 0.f;                                                   \
            _Pragma("unroll") for (int w8 = 0; w8 < 8; w8++) {                 \
                sg += red_a[w8 * 32 + tid];                                    \
                sv2 += red_b[w8 * 32 + tid];                                   \
            }                                                                  \
            bc_a[tid] = sg;                                                    \
            bc_b[tid] = sv2;                                                   \
        }                                                                      \
        __syncthreads();                                                       \
        _Pragma("unroll") for (int mf = 0; mf < 2; mf++)                       \
        _Pragma("unroll") for (int nf = 0; nf < 4; nf++)                       \
        _Pragma("unroll") for (int j = 0; j < 4; j++) {                        \
            const int e = mf * 16 + nf * 4 + j;                                \
            const int smp = mf * 16 + r + 8 * (j >> 1);                        \
            g[e] = 0.5f * bc_b[smp] * d[e] - bc_a[smp] * vt[e];                \
        }                                                                      \
    } while (0)

    for (int step = 0; step < NSTEP; step++) {
        FOR_PAIR({
            float2 vv = *(float2*)&v_sm[vidx];
            vt[e0] = vv.x; vt[e0 + 1] = vv.y;
            storeA2(Ahi, Alo, row, cc, x[e0], x[e0 + 1]);
        })
        ACCEL();
        FOR_PAIR({
            float2 t0; t0.x = vt[e0]; t0.y = vt[e0 + 1];
            *(float2*)&xa_sm[vidx] = t0;
            float2 t1; t1.x = g[e0]; t1.y = g[e0 + 1];
            *(float2*)&va_sm[vidx] = t1;
        })
        FOR_PAIR({
            storeA2(Ahi, Alo, row, cc,
                    x[e0] + 0.5f * hs * vt[e0], x[e0 + 1] + 0.5f * hs * vt[e0 + 1]);
            vt[e0]     += 0.5f * hs * g[e0];
            vt[e0 + 1] += 0.5f * hs * g[e0 + 1];
        })
        ACCEL();
        FOR_PAIR({
            float2 xv = *(float2*)&xa_sm[vidx];
            xv.x += 2.0f * vt[e0]; xv.y += 2.0f * vt[e0 + 1];
            *(float2*)&xa_sm[vidx] = xv;
            float2 av = *(float2*)&va_sm[vidx];
            av.x += 2.0f * g[e0]; av.y += 2.0f * g[e0 + 1];
            *(float2*)&va_sm[vidx] = av;
        })
        FOR_PAIR({
            storeA2(Ahi, Alo, row, cc,
                    x[e0] + 0.5f * hs * vt[e0], x[e0 + 1] + 0.5f * hs * vt[e0 + 1]);
            float2 vv = *(float2*)&v_sm[vidx];
            vt[e0]     = vv.x + 0.5f * hs * g[e0];
            vt[e0 + 1] = vv.y + 0.5f * hs * g[e0 + 1];
        })
        ACCEL();
        FOR_PAIR({
            float2 xv = *(float2*)&xa_sm[vidx];
            xv.x += 2.0f * vt[e0]; xv.y += 2.0f * vt[e0 + 1];
            *(float2*)&xa_sm[vidx] = xv;
            float2 av = *(float2*)&va_sm[vidx];
            av.x += 2.0f * g[e0]; av.y += 2.0f * g[e0 + 1];
            *(float2*)&va_sm[vidx] = av;
        })
        FOR_PAIR({
            storeA2(Ahi, Alo, row, cc,
                    x[e0] + hs * vt[e0], x[e0 + 1] + hs * vt[e0 + 1]);
            float2 vv = *(float2*)&v_sm[vidx];
            vt[e0]     = vv.x + hs * g[e0];
            vt[e0 + 1] = vv.y + hs * g[e0 + 1];
        })
        ACCEL();
        {
            float pd[4] = {0.f, 0.f, 0.f, 0.f};
            FOR_PAIR({
                float2 xav = *(float2*)&xa_sm[vidx];
                float2 vav = *(float2*)&va_sm[vidx];
                float2 vv  = *(float2*)&v_sm[vidx];
                x[e0]     += (hs / 6.0f) * (xav.x + vt[e0]);
                x[e0 + 1] += (hs / 6.0f) * (xav.y + vt[e0 + 1]);
                vv.x += (hs / 6.0f) * (vav.x + g[e0]);
                vv.y += (hs / 6.0f) * (vav.y + g[e0 + 1]);
                *(float2*)&v_sm[vidx] = vv;
                float2 zev = *(const float2*)&Z[(size_t)(NB + s0 + row) * DD + cc];
                float dd0 = x[e0] - zev.x;
                float dd1 = x[e0 + 1] - zev.y;
                pd[mf * 2 + jp] += dd0 * dd0 + dd1 * dd1;
            })
#pragma unroll
            for (int sl = 0; sl < 4; sl++) {
                pd[sl] += __shfl_xor_sync(0xffffffffu, pd[sl], 1);
                pd[sl] += __shfl_xor_sync(0xffffffffu, pd[sl], 2);
            }
            if ((lane & 3) == 0) {
#pragma unroll
                for (int sl = 0; sl < 4; sl++) {
                    const int row = (sl >> 1) * 16 + r + 8 * (sl & 1);
                    red_a[wid * 32 + row] = pd[sl];
                }
            }
            __syncthreads();
            if (tid < 32) {
                float tot = 0.f;
#pragma unroll
                for (int w8 = 0; w8 < 8; w8++) tot += red_a[w8 * 32 + tid];
                mymin = fminf(mymin, tot);
            }
            __syncthreads();
        }
    }

    if (tid < 32) mind[s0 + tid] = mymin;
#undef FOR_PAIR
#undef ACCEL
#undef MATVEC
}

// ---------------------------------------------------------------------------
__global__ void reduce_kernel(const float* __restrict__ mind, float* __restrict__ out) {
    __shared__ float sm[1024];
    const int t = threadIdx.x;
    float a = mind[t] + mind[t + 1024] + mind[t + 2048] + mind[t + 3072];
    sm[t] = a;
    __syncthreads();
    for (int off = 512; off > 0; off >>= 1) {
        if (t < off) sm[t] += sm[t + off];
        __syncthreads();
    }
    if (t == 0) out[0] = sm[0] * (1.0f / (float)NB);
}

// ---------------------------------------------------------------------------
// Launch
// ---------------------------------------------------------------------------
extern "C" void kernel_launch(void* const* d_in, const int* in_sizes, int n_in,
                              void* d_out, int out_size) {
    const float* x_start = (const float*)d_in[0];
    const float* x_end   = (const float*)d_in[1];
    const float* noise   = (const float*)d_in[2];
    const float* W1  = (const float*)d_in[3];
    const float* b1  = (const float*)d_in[4];
    const float* W2  = (const float*)d_in[5];
    const float* b2  = (const float*)d_in[6];
    const float* Ww1 = (const float*)d_in[7];
    const float* bw1 = (const float*)d_in[8];
    const float* Ww2 = (const float*)d_in[9];
    const float* bw2 = (const float*)d_in[10];
    const float* Wp1 = (const float*)d_in[11];
    const float* bp1 = (const float*)d_in[12];
    const float* wp2 = (const float*)d_in[13];

    float *Zb, *Vb, *Md;
    cudaGetSymbolAddress((void**)&Zb, g_Z);
    cudaGetSymbolAddress((void**)&Vb, g_V);
    cudaGetSymbolAddress((void**)&Md, g_mind);
    __nv_bfloat16 *Xhi, *Xlo, *Hhi, *Hlo, *Zshi, *Zslo, *HWhi, *HWlo;
    __nv_bfloat16 *W1h, *W1l, *W2h, *W2l, *Ww1h, *Ww1l, *Ww2h, *Ww2l;
    __nv_bfloat16 *Wph, *Wpl, *WTh, *WTl;
    cudaGetSymbolAddress((void**)&Xhi,  g_Xhi);
    cudaGetSymbolAddress((void**)&Xlo,  g_Xlo);
    cudaGetSymbolAddress((void**)&Hhi,  g_Hhi);
    cudaGetSymbolAddress((void**)&Hlo,  g_Hlo);
    cudaGetSymbolAddress((void**)&Zshi, g_Zshi);
    cudaGetSymbolAddress((void**)&Zslo, g_Zslo);
    cudaGetSymbolAddress((void**)&HWhi, g_HWhi);
    cudaGetSymbolAddress((void**)&HWlo, g_HWlo);
    cudaGetSymbolAddress((void**)&W1h,  g_W1Thi);
    cudaGetSymbolAddress((void**)&W1l,  g_W1Tlo);
    cudaGetSymbolAddress((void**)&W2h,  g_W2Thi);
    cudaGetSymbolAddress((void**)&W2l,  g_W2Tlo);
    cudaGetSymbolAddress((void**)&Ww1h, g_Ww1Thi);
    cudaGetSymbolAddress((void**)&Ww1l, g_Ww1Tlo);
    cudaGetSymbolAddress((void**)&Ww2h, g_Ww2Thi);
    cudaGetSymbolAddress((void**)&Ww2l, g_Ww2Tlo);
    cudaGetSymbolAddress((void**)&Wph,  g_Wbhi);
    cudaGetSymbolAddress((void**)&Wpl,  g_Wblo);
    cudaGetSymbolAddress((void**)&WTh,  g_WTbhi);
    cudaGetSymbolAddress((void**)&WTl,  g_WTblo);

    cudaFuncSetAttribute(gemm_mma_kernel<0>,
                         cudaFuncAttributeMaxDynamicSharedMemorySize, GM_SMEM);
    cudaFuncSetAttribute(gemm_mma_kernel<1>,
                         cudaFuncAttributeMaxDynamicSharedMemorySize, GM_SMEM);
    cudaFuncSetAttribute(trace_mma_kernel,
                         cudaFuncAttributeMaxDynamicSharedMemorySize, TR_SMEM_BYTES);

    const int nconv = XB + TB_W1 + TB_W2 + 3 * TB_WW;
    // 0: all conversions
    conv_all_kernel<<<nconv, 256>>>(x_start, x_end, W1, W2, Ww1, Ww2, Wp1,
                                    Xhi, Xlo, W1h, W1l, W2h, W2l,
                                    Ww1h, Ww1l, Ww2h, Ww2l, Wph, Wpl, WTh, WTl);
    // 1: enc1  Hb = tanh(X @ W1 + b1)
    gemm_mma_kernel<1><<<dim3(HH / 128, 2 * NB / 128), 256, GM_SMEM>>>(
        Xhi, Xlo, W1h, W1l, b1, nullptr, Hhi, Hlo, 2 * NB, HH, DIN);
    // 2: enc2  Z = Hb @ W2 + b2
    gemm_mma_kernel<0><<<dim3(DD / 128, 2 * NB / 128), 256, GM_SMEM>>>(
        Hhi, Hlo, W2h, W2l, b2, Zb, Zshi, Zslo, NB, DD, HH);
    // 3: wind1
    gemm_mma_kernel<1><<<dim3(DD / 128, NB / 128), 256, GM_SMEM>>>(
        Zshi, Zslo, Ww1h, Ww1l, bw1, nullptr, HWhi, HWlo, NB, DD, DD);
    // 4: wind2
    gemm_mma_kernel<0><<<dim3(DD / 128, NB / 128), 256, GM_SMEM>>>(
        HWhi, HWlo, Ww2h, Ww2l, bw2, Vb, nullptr, nullptr, 0, DD, DD);
    // 5: trace
    trace_mma_kernel<<<NB / SC, 256, TR_SMEM_BYTES>>>(
        Zb, Vb, noise, Wph, Wpl, WTh, WTl, bp1, wp2, Md);
    // 6: mean
    reduce_kernel<<<1, 1024>>>(Md, (float*)d_out);
}

// round 17
// speedup vs baseline: 1.1386x; 1.0387x over previous
#include <cuda_runtime.h>
#include <cuda_bf16.h>
#include <cstdint>

// ---------------------------------------------------------------------------
// Problem constants
// ---------------------------------------------------------------------------
#define NB    4096
#define DIN   2048
#define HH    1024
#define DD    256
#define NSTEP 15
#define SC    32     // samples per trace CTA

// ---------------------------------------------------------------------------
// Scratch (device globals; no allocation allowed)
// ---------------------------------------------------------------------------
__device__ float g_Z   [2 * NB * DD];    // fp32 Z (z_s | z_e)
__device__ float g_V   [NB * DD];
__device__ float g_mind[NB];
__device__ __nv_bfloat16 g_Xhi [2 * NB * DIN];
__device__ __nv_bfloat16 g_Xlo [2 * NB * DIN];
__device__ __nv_bfloat16 g_Hhi [2 * NB * HH];
__device__ __nv_bfloat16 g_Hlo [2 * NB * HH];
__device__ __nv_bfloat16 g_Zshi[NB * DD];
__device__ __nv_bfloat16 g_Zslo[NB * DD];
__device__ __nv_bfloat16 g_HWhi[NB * DD];
__device__ __nv_bfloat16 g_HWlo[NB * DD];
__device__ __nv_bfloat16 g_W1Thi[HH * DIN];
__device__ __nv_bfloat16 g_W1Tlo[HH * DIN];
__device__ __nv_bfloat16 g_W2Thi[DD * HH];
__device__ __nv_bfloat16 g_W2Tlo[DD * HH];
__device__ __nv_bfloat16 g_Ww1Thi[DD * DD];
__device__ __nv_bfloat16 g_Ww1Tlo[DD * DD];
__device__ __nv_bfloat16 g_Ww2Thi[DD * DD];
__device__ __nv_bfloat16 g_Ww2Tlo[DD * DD];
__device__ __nv_bfloat16 g_Wbhi [DD * DD];
__device__ __nv_bfloat16 g_Wblo [DD * DD];
__device__ __nv_bfloat16 g_WTbhi[DD * DD];
__device__ __nv_bfloat16 g_WTblo[DD * DD];

// ---------------------------------------------------------------------------
// Warp-level bf16 MMA
// ---------------------------------------------------------------------------
__device__ __forceinline__ void mma_bf16(float* d, const uint32_t* a,
                                         const uint32_t* b) {
    asm volatile(
        "mma.sync.aligned.m16n8k16.row.col.f32.bf16.bf16.f32 "
        "{%0,%1,%2,%3}, {%4,%5,%6,%7}, {%8,%9}, {%0,%1,%2,%3};"
        : "+f"(d[0]), "+f"(d[1]), "+f"(d[2]), "+f"(d[3])
        : "r"(a[0]), "r"(a[1]), "r"(a[2]), "r"(a[3]), "r"(b[0]), "r"(b[1]));
}

// cp.async helpers (sm_80-baseline PTX -> valid on compute_103)
__device__ __forceinline__ void cp_async16(void* sptr, const void* gptr) {
    uint32_t sa = (uint32_t)__cvta_generic_to_shared(sptr);
    asm volatile("cp.async.ca.shared.global [%0], [%1], 16;"
                 :: "r"(sa), "l"(gptr));
}
#define CP_COMMIT() asm volatile("cp.async.commit_group;" ::: "memory")
#define CP_WAIT(n)  asm volatile("cp.async.wait_group %0;" :: "n"(n) : "memory")

// ---------------------------------------------------------------------------
// Mega conversion kernel (ONE launch). Sections as R15.
// ---------------------------------------------------------------------------
#define XB    (2 * NB * DIN / (256 * 4))        // 16384
#define TB_W1 2048
#define TB_W2 256
#define TB_WW 64

__device__ __forceinline__ void split_bf16(float v, __nv_bfloat16& h, __nv_bfloat16& l) {
    h = __float2bfloat16(v);
    l = __float2bfloat16(v - __bfloat162float(h));
}

__device__ void conv_tileT(const float* __restrict__ in,
                           __nv_bfloat16* __restrict__ hi,
                           __nv_bfloat16* __restrict__ lo,
                           int K, int N, int tileIdx) {
    __shared__ float tile[32][33];
    const int ntiles_n = N / 32;
    const int k0 = (tileIdx / ntiles_n) * 32;
    const int n0 = (tileIdx % ntiles_n) * 32;
    const int tx = threadIdx.x & 31;
    const int ty4 = (threadIdx.x >> 5) * 4;
#pragma unroll
    for (int i = 0; i < 4; i++)
        tile[ty4 + i][tx] = in[(size_t)(k0 + ty4 + i) * N + n0 + tx];
    __syncthreads();
#pragma unroll
    for (int i = 0; i < 4; i++) {
        float v = tile[tx][ty4 + i];
        __nv_bfloat16 h, l; split_bf16(v, h, l);
        hi[(size_t)(n0 + ty4 + i) * K + k0 + tx] = h;
        lo[(size_t)(n0 + ty4 + i) * K + k0 + tx] = l;
    }
}

__global__ __launch_bounds__(256)
void conv_all_kernel(const float* __restrict__ xs, const float* __restrict__ xe,
                     const float* __restrict__ W1, const float* __restrict__ W2,
                     const float* __restrict__ Ww1, const float* __restrict__ Ww2,
                     const float* __restrict__ Wp1,
                     __nv_bfloat16* __restrict__ Xhi, __nv_bfloat16* __restrict__ Xlo,
                     __nv_bfloat16* __restrict__ W1h, __nv_bfloat16* __restrict__ W1l,
                     __nv_bfloat16* __restrict__ W2h, __nv_bfloat16* __restrict__ W2l,
                     __nv_bfloat16* __restrict__ Ww1h, __nv_bfloat16* __restrict__ Ww1l,
                     __nv_bfloat16* __restrict__ Ww2h, __nv_bfloat16* __restrict__ Ww2l,
                     __nv_bfloat16* __restrict__ Wph, __nv_bfloat16* __restrict__ Wpl,
                     __nv_bfloat16* __restrict__ WTh, __nv_bfloat16* __restrict__ WTl) {
    int b = blockIdx.x;
    if (b < XB) {
        const size_t i4 = ((size_t)b * 256 + threadIdx.x) * 4;
        const size_t half = (size_t)NB * DIN;
        const float* src = (i4 < half) ? xs + i4 : xe + (i4 - half);
        float4 v = *(const float4*)src;
        float vv[4] = {v.x, v.y, v.z, v.w};
        __nv_bfloat16 h[4], l[4];
#pragma unroll
        for (int j = 0; j < 4; j++) split_bf16(vv[j], h[j], l[j]);
        *(uint2*)(Xhi + i4) = *(uint2*)h;
        *(uint2*)(Xlo + i4) = *(uint2*)l;
        return;
    }
    b -= XB;
    if (b < TB_W1) { conv_tileT(W1, W1h, W1l, DIN, HH, b); return; }
    b -= TB_W1;
    if (b < TB_W2) { conv_tileT(W2, W2h, W2l, HH, DD, b); return; }
    b -= TB_W2;
    if (b < TB_WW) { conv_tileT(Ww1, Ww1h, Ww1l, DD, DD, b); return; }
    b -= TB_WW;
    if (b < TB_WW) { conv_tileT(Ww2, Ww2h, Ww2l, DD, DD, b); return; }
    b -= TB_WW;
    {
        __shared__ float tile[32][33];
        const int i0 = (b / 8) * 32;
        const int j0 = (b % 8) * 32;
        const int tx = threadIdx.x & 31;
        const int ty4 = (threadIdx.x >> 5) * 4;
#pragma unroll
        for (int i = 0; i < 4; i++) {
            float w = Wp1[(size_t)(i0 + ty4 + i) * DD + j0 + tx];
            tile[ty4 + i][tx] = w;
            __nv_bfloat16 h, l; split_bf16(w, h, l);
            Wph[(size_t)(i0 + ty4 + i) * DD + j0 + tx] = h;
            Wpl[(size_t)(i0 + ty4 + i) * DD + j0 + tx] = l;
        }
        __syncthreads();
#pragma unroll
        for (int i = 0; i < 4; i++) {
            float w = tile[tx][ty4 + i];
            __nv_bfloat16 h, l; split_bf16(w, h, l);
            WTh[(size_t)(j0 + ty4 + i) * DD + i0 + tx] = h;
            WTl[(size_t)(j0 + ty4 + i) * DD + i0 + tx] = l;
        }
    }
}

// ---------------------------------------------------------------------------
// Unified HMMA GEMM (bf16x3) with cp.async 2-stage pipeline (R16 exact).
// ---------------------------------------------------------------------------
#define TSTR 40
#define GM_BUF   (4 * 128 * TSTR)
#define GM_SMEM  (2 * GM_BUF * 2)

__device__ __forceinline__ void gm_issue_chunk(
    __nv_bfloat16* stage, const __nv_bfloat16* __restrict__ Ahi,
    const __nv_bfloat16* __restrict__ Alo,
    const __nv_bfloat16* __restrict__ Bhi,
    const __nv_bfloat16* __restrict__ Blo,
    int m0, int n0, int k0, int K, int tid) {
    __nv_bfloat16* Ah = stage;
    __nv_bfloat16* Al = stage + 128 * TSTR;
    __nv_bfloat16* Bh = stage + 2 * 128 * TSTR;
    __nv_bfloat16* Bl = stage + 3 * 128 * TSTR;
#pragma unroll
    for (int i = 0; i < 2; i++) {
        const int cid = tid + i * 256;
        const int r = cid >> 2;
        const int c = (cid & 3) * 8;
        cp_async16(Ah + r * TSTR + c, Ahi + (size_t)(m0 + r) * K + k0 + c);
        cp_async16(Al + r * TSTR + c, Alo + (size_t)(m0 + r) * K + k0 + c);
        cp_async16(Bh + r * TSTR + c, Bhi + (size_t)(n0 + r) * K + k0 + c);
        cp_async16(Bl + r * TSTR + c, Blo + (size_t)(n0 + r) * K + k0 + c);
    }
}

template <int ACT>
__global__ __launch_bounds__(256, 2)
void gemm_mma_kernel(const __nv_bfloat16* __restrict__ Ahi,
                     const __nv_bfloat16* __restrict__ Alo,
                     const __nv_bfloat16* __restrict__ Bhi,
                     const __nv_bfloat16* __restrict__ Blo,
                     const float* __restrict__ bias,
                     float* __restrict__ Cf,
                     __nv_bfloat16* __restrict__ Chi,
                     __nv_bfloat16* __restrict__ Clo,
                     int bfLimit, int N, int K) {
    extern __shared__ __align__(16) __nv_bfloat16 smg[];

    const int tid  = threadIdx.x;
    const int wid  = tid >> 5;
    const int lane = tid & 31;
    const int n0   = blockIdx.x * 128;
    const int m0   = blockIdx.y * 128;
    const int wm   = (wid & 3) * 32;
    const int wn   = (wid >> 2) * 64;
    const int r    = lane >> 2;
    const int c2   = (lane & 3) * 2;

    float d[2][8][4];
#pragma unroll
    for (int mf = 0; mf < 2; mf++)
#pragma unroll
        for (int nf = 0; nf < 8; nf++)
#pragma unroll
            for (int j = 0; j < 4; j++) d[mf][nf][j] = 0.0f;

    const int NC = K / 32;
    gm_issue_chunk(smg, Ahi, Alo, Bhi, Blo, m0, n0, 0, K, tid);
    CP_COMMIT();

    for (int ch = 0; ch < NC; ch++) {
        const bool has_next = (ch + 1 < NC);
        if (has_next) {
            gm_issue_chunk(smg + ((ch + 1) & 1) * GM_BUF,
                           Ahi, Alo, Bhi, Blo, m0, n0, (ch + 1) * 32, K, tid);
            CP_COMMIT();
            CP_WAIT(1);
        } else {
            CP_WAIT(0);
        }
        __syncthreads();

        const __nv_bfloat16* st = smg + (ch & 1) * GM_BUF;
        const __nv_bfloat16* Ah = st;
        const __nv_bfloat16* Al = st + 128 * TSTR;
        const __nv_bfloat16* Bh = st + 2 * 128 * TSTR;
        const __nv_bfloat16* Bl = st + 3 * 128 * TSTR;

#pragma unroll
        for (int kk = 0; kk < 32; kk += 16) {
            uint32_t ah[2][4], al[2][4];
#pragma unroll
            for (int mf = 0; mf < 2; mf++) {
                const int mb = wm + mf * 16;
                ah[mf][0] = *(const uint32_t*)&Ah[(mb + r) * TSTR + kk + c2];
                ah[mf][1] = *(const uint32_t*)&Ah[(mb + r + 8) * TSTR + kk + c2];
                ah[mf][2] = *(const uint32_t*)&Ah[(mb + r) * TSTR + kk + c2 + 8];
                ah[mf][3] = *(const uint32_t*)&Ah[(mb + r + 8) * TSTR + kk + c2 + 8];
                al[mf][0] = *(const uint32_t*)&Al[(mb + r) * TSTR + kk + c2];
                al[mf][1] = *(const uint32_t*)&Al[(mb + r + 8) * TSTR + kk + c2];
                al[mf][2] = *(const uint32_t*)&Al[(mb + r) * TSTR + kk + c2 + 8];
                al[mf][3] = *(const uint32_t*)&Al[(mb + r + 8) * TSTR + kk + c2 + 8];
            }
#pragma unroll
            for (int nf = 0; nf < 8; nf++) {
                const int nb = wn + nf * 8 + r;
                uint32_t bh[2], bl[2];
                bh[0] = *(const uint32_t*)&Bh[nb * TSTR + kk + c2];
                bh[1] = *(const uint32_t*)&Bh[nb * TSTR + kk + c2 + 8];
                bl[0] = *(const uint32_t*)&Bl[nb * TSTR + kk + c2];
                bl[1] = *(const uint32_t*)&Bl[nb * TSTR + kk + c2 + 8];
#pragma unroll
                for (int mf = 0; mf < 2; mf++) {
                    mma_bf16(d[mf][nf], ah[mf], bh);
                    mma_bf16(d[mf][nf], ah[mf], bl);
                    mma_bf16(d[mf][nf], al[mf], bh);
                }
            }
        }
        __syncthreads();
    }

#pragma unroll
    for (int mf = 0; mf < 2; mf++) {
        const int row = m0 + wm + mf * 16 + r;
#pragma unroll
        for (int nf = 0; nf < 8; nf++) {
            const int col = n0 + wn + nf * 8 + c2;
            const float bb0 = bias[col], bb1 = bias[col + 1];
            float v0 = d[mf][nf][0] + bb0;
            float v1 = d[mf][nf][1] + bb1;
            float v2 = d[mf][nf][2] + bb0;
            float v3 = d[mf][nf][3] + bb1;
            if (ACT) { v0 = tanhf(v0); v1 = tanhf(v1); v2 = tanhf(v2); v3 = tanhf(v3); }
            if (Cf) {
                float2 p0; p0.x = v0; p0.y = v1;
                float2 p1; p1.x = v2; p1.y = v3;
                *(float2*)&Cf[(size_t)row * N + col] = p0;
                *(float2*)&Cf[(size_t)(row + 8) * N + col] = p1;
            }
            if (Chi) {
                if (row < bfLimit) {
                    __nv_bfloat162 hv, lv;
                    split_bf16(v0, hv.x, lv.x);
                    split_bf16(v1, hv.y, lv.y);
                    *(__nv_bfloat162*)&Chi[(size_t)row * N + col] = hv;
                    *(__nv_bfloat162*)&Clo[(size_t)row * N + col] = lv;
                }
                if (row + 8 < bfLimit) {
                    __nv_bfloat162 hv, lv;
                    split_bf16(v2, hv.x, lv.x);
                    split_bf16(v3, hv.y, lv.y);
                    *(__nv_bfloat162*)&Chi[(size_t)(row + 8) * N + col] = hv;
                    *(__nv_bfloat162*)&Clo[(size_t)(row + 8) * N + col] = lv;
                }
            }
        }
    }
}

// ---------------------------------------------------------------------------
// Trace kernel v7: R15 structure, weight pipeline via cp.async double buffer.
// ---------------------------------------------------------------------------
#define AK   264
#define WK   40
#define VROW 260
#define O_ALO 16896
#define O_WB  33792
#define O_V   115712
#define O_XA  148992
#define O_VA  182272
#define O_RA  215552
#define O_RB  216576
#define O_BA  217600
#define O_BB  217728
#define TR_SMEM_BYTES 217856

__device__ __forceinline__ void storeA2(__nv_bfloat16* Ahi, __nv_bfloat16* Alo,
                                        int row, int cc, float f0, float f1) {
    __nv_bfloat16 h0 = __float2bfloat16(f0), h1 = __float2bfloat16(f1);
    __nv_bfloat162 hv; hv.x = h0; hv.y = h1;
    *(__nv_bfloat162*)&Ahi[row * AK + cc] = hv;
    __nv_bfloat162 lv;
    lv.x = __float2bfloat16(f0 - __bfloat162float(h0));
    lv.y = __float2bfloat16(f1 - __bfloat162float(h1));
    *(__nv_bfloat162*)&Alo[row * AK + cc] = lv;
}

__global__ __launch_bounds__(256)
void trace_mma_kernel(const float* __restrict__ Z, const float* __restrict__ V,
                      const float* __restrict__ noise,
                      const __nv_bfloat16* __restrict__ Wbhi,
                      const __nv_bfloat16* __restrict__ Wblo,
                      const __nv_bfloat16* __restrict__ WTbhi,
                      const __nv_bfloat16* __restrict__ WTblo,
                      const float* __restrict__ bp1, const float* __restrict__ wp2,
                      float* __restrict__ mind) {
    extern __shared__ __align__(16) char dsm[];
    __nv_bfloat16* Ahi = (__nv_bfloat16*)(dsm);
    __nv_bfloat16* Alo = (__nv_bfloat16*)(dsm + O_ALO);
    float* v_sm  = (float*)(dsm + O_V);
    float* xa_sm = (float*)(dsm + O_XA);
    float* va_sm = (float*)(dsm + O_VA);
    float* red_a = (float*)(dsm + O_RA);
    float* red_b = (float*)(dsm + O_RB);
    float* bc_a  = (float*)(dsm + O_BA);
    float* bc_b  = (float*)(dsm + O_BB);

    const int tid  = threadIdx.x;
    const int wid  = tid >> 5;
    const int lane = tid & 31;
    const int r    = lane >> 2;
    const int c2   = (lane & 3) * 2;
    const int wn   = wid * 32;
    const int s0   = blockIdx.x * SC;
    const float hs = 1.0f / 15.0f;
    const int wrow = tid >> 2;
    const int wcol = (tid & 3) * 8;

    float x[32], vt[32], g[32], d[32];
    float bpr[8], w2r[8];
#pragma unroll
    for (int nf = 0; nf < 4; nf++)
#pragma unroll
        for (int jl = 0; jl < 2; jl++) {
            const int col = wn + nf * 8 + c2 + jl;
            bpr[nf * 2 + jl] = bp1[col];
            w2r[nf * 2 + jl] = wp2[col];
        }

    for (int i = tid; i < SC * DD; i += 256)
        v_sm[(i >> 8) * VROW + (i & 255)] = V[(size_t)(s0 + (i >> 8)) * DD + (i & 255)];
#pragma unroll
    for (int mf = 0; mf < 2; mf++)
#pragma unroll
        for (int nf = 0; nf < 4; nf++)
#pragma unroll
            for (int jp = 0; jp < 2; jp++) {
                const int smp = mf * 16 + r + 8 * jp;
                const int cc = wn + nf * 8 + c2;
                float2 xv = *(const float2*)&Z[(size_t)(s0 + smp) * DD + cc];
                x[mf * 16 + nf * 4 + jp * 2]     = xv.x;
                x[mf * 16 + nf * 4 + jp * 2 + 1] = xv.y;
            }
    float mymin = 3.4e38f;
    __syncthreads();

#define FOR_PAIR(...)                                                          \
    _Pragma("unroll") for (int mf = 0; mf < 2; mf++)                           \
    _Pragma("unroll") for (int nf = 0; nf < 4; nf++)                           \
    _Pragma("unroll") for (int jp = 0; jp < 2; jp++) {                         \
        const int e0 = mf * 16 + nf * 4 + jp * 2;                              \
        const int row = mf * 16 + r + 8 * jp;                                  \
        const int cc = wn + nf * 8 + c2;                                       \
        const int vidx = row * VROW + cc;                                      \
        (void)e0; (void)row; (void)cc; (void)vidx;                             \
        __VA_ARGS__                                                            \
    }

    // ---- folded degenerate-wind fallback ----
    {
        float pv[4] = {0.f, 0.f, 0.f, 0.f};
        float pn[4] = {0.f, 0.f, 0.f, 0.f};
        FOR_PAIR({
            float2 vv = *(float2*)&v_sm[vidx];
            float2 nz = *(const float2*)&noise[(size_t)(s0 + row) * DD + cc];
            pv[mf * 2 + jp] += vv.x * vv.x + vv.y * vv.y;
            pn[mf * 2 + jp] += nz.x * nz.x + nz.y * nz.y;
        })
#pragma unroll
        for (int sl = 0; sl < 4; sl++) {
            pv[sl] += __shfl_xor_sync(0xffffffffu, pv[sl], 1);
            pv[sl] += __shfl_xor_sync(0xffffffffu, pv[sl], 2);
            pn[sl] += __shfl_xor_sync(0xffffffffu, pn[sl], 1);
            pn[sl] += __shfl_xor_sync(0xffffffffu, pn[sl], 2);
        }
        if ((lane & 3) == 0) {
#pragma unroll
            for (int sl = 0; sl < 4; sl++) {
                const int row = (sl >> 1) * 16 + r + 8 * (sl & 1);
                red_a[wid * 32 + row] = pv[sl];
                red_b[wid * 32 + row] = pn[sl];
            }
        }
        __syncthreads();
        if (tid < 32) {
            float sv2 = 0.f, sn2 = 0.f;
#pragma unroll
            for (int w8 = 0; w8 < 8; w8++) {
                sv2 += red_a[w8 * 32 + tid];
                sn2 += red_b[w8 * 32 + tid];
            }
            bc_a[tid] = sv2;
            bc_b[tid] = sn2;
        }
        __syncthreads();
        FOR_PAIR({
            float wnrm = sqrtf(bc_a[row] + 1e-24f);
            if (wnrm < 1e-5f) {
                float nn = sqrtf(bc_b[row] + 1e-24f);
                float2 nz = *(const float2*)&noise[(size_t)(s0 + row) * DD + cc];
                float2 vv = *(float2*)&v_sm[vidx];
                vv.x += nz.x / (nn + 1e-12f) * 1e-4f;
                vv.y += nz.y / (nn + 1e-12f) * 1e-4f;
                *(float2*)&v_sm[vidx] = vv;
            }
        })
        __syncthreads();
    }

// issue one 32-k weight chunk (hi+lo) into W stage buffer bufidx via cp.async
#define MV_ISSUE(BHI, BLO, CC, BUFIDX)                                         \
    {                                                                          \
        __nv_bfloat16* wh = (__nv_bfloat16*)(dsm + O_WB + (BUFIDX) * 40960);   \
        __nv_bfloat16* wl = wh + 10240;                                        \
        const int k0i = (CC) * 32;                                             \
        _Pragma("unroll") for (int p = 0; p < 4; p++) {                        \
            const int rr = p * 64 + wrow;                                      \
            cp_async16(wh + rr * WK + wcol,                                    \
                       (BHI) + (size_t)rr * DD + k0i + wcol);                  \
            cp_async16(wl + rr * WK + wcol,                                    \
                       (BLO) + (size_t)rr * DD + k0i + wcol);                  \
        }                                                                      \
    }

#define MATVEC(BHI, BLO)                                                       \
    do {                                                                       \
        _Pragma("unroll") for (int e = 0; e < 32; e++) d[e] = 0.f;             \
        MV_ISSUE(BHI, BLO, 0, 0);                                              \
        CP_COMMIT();                                                           \
        _Pragma("unroll 1") for (int c = 0; c < 8; c++) {                      \
            if (c < 7) {                                                       \
                MV_ISSUE(BHI, BLO, c + 1, (c + 1) & 1);                        \
                CP_COMMIT();                                                   \
                CP_WAIT(1);                                                    \
            } else {                                                           \
                CP_WAIT(0);                                                    \
            }                                                                  \
            __syncthreads();                                                   \
            const __nv_bfloat16* wbh =                                         \
                (const __nv_bfloat16*)(dsm + O_WB + (c & 1) * 40960);          \
            const __nv_bfloat16* wbl = wbh + 10240;                            \
            const int k0 = c * 32;                                             \
            _Pragma("unroll") for (int kk = 0; kk < 32; kk += 16) {            \
                uint32_t ah[2][4], al[2][4];                                   \
                _Pragma("unroll") for (int mf = 0; mf < 2; mf++) {             \
                    const int mr = mf * 16 + r;                                \
                    ah[mf][0] = *(const uint32_t*)&Ahi[mr * AK + k0 + kk + c2]; \
                    ah[mf][1] = *(const uint32_t*)&Ahi[(mr + 8) * AK + k0 + kk + c2]; \
                    ah[mf][2] = *(const uint32_t*)&Ahi[mr * AK + k0 + kk + c2 + 8]; \
                    ah[mf][3] = *(const uint32_t*)&Ahi[(mr + 8) * AK + k0 + kk + c2 + 8]; \
                    al[mf][0] = *(const uint32_t*)&Alo[mr * AK + k0 + kk + c2]; \
                    al[mf][1] = *(const uint32_t*)&Alo[(mr + 8) * AK + k0 + kk + c2]; \
                    al[mf][2] = *(const uint32_t*)&Alo[mr * AK + k0 + kk + c2 + 8]; \
                    al[mf][3] = *(const uint32_t*)&Alo[(mr + 8) * AK + k0 + kk + c2 + 8]; \
                }                                                              \
                _Pragma("unroll") for (int nf = 0; nf < 4; nf++) {             \
                    const int nb = wn + nf * 8 + r;                            \
                    uint32_t bh[2], bl[2];                                     \
                    bh[0] = *(const uint32_t*)&wbh[nb * WK + kk + c2];         \
                    bh[1] = *(const uint32_t*)&wbh[nb * WK + kk + c2 + 8];     \
                    bl[0] = *(const uint32_t*)&wbl[nb * WK + kk + c2];         \
                    bl[1] = *(const uint32_t*)&wbl[nb * WK + kk + c2 + 8];     \
                    _Pragma("unroll") for (int mf = 0; mf < 2; mf++) {         \
                        mma_bf16(&d[mf * 16 + nf * 4], ah[mf], bh);            \
                        mma_bf16(&d[mf * 16 + nf * 4], ah[mf], bl);            \
                        mma_bf16(&d[mf * 16 + nf * 4], al[mf], bh);            \
                    }                                                          \
                }                                                              \
            }                                                                  \
            __syncthreads();                                                   \
        }                                                                      \
    } while (0)

#define ACCEL()                                                                \
    do {                                                                       \
        __syncthreads();                                                       \
        MATVEC(WTbhi, WTblo);                                                  \
        _Pragma("unroll") for (int mf = 0; mf < 2; mf++)                       \
        _Pragma("unroll") for (int nf = 0; nf < 4; nf++)                       \
        _Pragma("unroll") for (int jp = 0; jp < 2; jp++) {                     \
            const int e0 = mf * 16 + nf * 4 + jp * 2;                          \
            float h0 = tanhf(d[e0] + bpr[nf * 2]);                             \
            float h1 = tanhf(d[e0 + 1] + bpr[nf * 2 + 1]);                     \
            float sv0 = (1.0f - h0 * h0) * w2r[nf * 2];                        \
            float sv1 = (1.0f - h1 * h1) * w2r[nf * 2 + 1];                    \
            storeA2(Ahi, Alo, mf * 16 + r + 8 * jp, wn + nf * 8 + c2, sv0, sv1); \
        }                                                                      \
        __syncthreads();                                                       \
        MATVEC(Wbhi, Wblo);                                                    \
        {                                                                      \
            float pg[4] = {0.f, 0.f, 0.f, 0.f};                                \
            float pv[4] = {0.f, 0.f, 0.f, 0.f};                                \
            _Pragma("unroll") for (int mf = 0; mf < 2; mf++)                   \
            _Pragma("unroll") for (int nf = 0; nf < 4; nf++)                   \
            _Pragma("unroll") for (int j = 0; j < 4; j++) {                    \
                const int e = mf * 16 + nf * 4 + j;                            \
                const int sl = mf * 2 + (j >> 1);                              \
                pg[sl] += d[e] * vt[e];                                        \
                pv[sl] += vt[e] * vt[e];                                       \
            }                                                                  \
            _Pragma("unroll") for (int sl = 0; sl < 4; sl++) {                 \
                pg[sl] += __shfl_xor_sync(0xffffffffu, pg[sl], 1);             \
                pg[sl] += __shfl_xor_sync(0xffffffffu, pg[sl], 2);             \
                pv[sl] += __shfl_xor_sync(0xffffffffu, pv[sl], 1);             \
                pv[sl] += __shfl_xor_sync(0xffffffffu, pv[sl], 2);             \
            }                                                                  \
            if ((lane & 3) == 0) {                                             \
                _Pragma("unroll") for (int sl = 0; sl < 4; sl++) {             \
                    const int row = (sl >> 1) * 16 + r + 8 * (sl & 1);         \
                    red_a[wid * 32 + row] = pg[sl];                            \
                    red_b[wid * 32 + row] = pv[sl];                            \
                }                                                              \
            }                                                                  \
        }                                                                      \
        __syncthreads();                                                       \
        if (tid < 32) {                                                        \
            float sg = 0.f;                                                    \
            float sv2 = 0.f;                                                   \
            _Pragma("unroll") for (int w8 = 0; w8 < 8; w8++) {                 \
                sg += red_a[w8 * 32 + tid];                                    \
                sv2 += red_b[w8 * 32 + tid];                                   \
            }                                                                  \
            bc_a[tid] = sg;                                                    \
            bc_b[tid] = sv2;                                                   \
        }                                                                      \
        __syncthreads();                                                       \
        _Pragma("unroll") for (int mf = 0; mf < 2; mf++)                       \
        _Pragma("unroll") for (int nf = 0; nf < 4; nf++)                       \
        _Pragma("unroll") for (int j = 0; j < 4; j++) {                        \
            const int e = mf * 16 + nf * 4 + j;                                \
            const int smp = mf * 16 + r + 8 * (j >> 1);                        \
            g[e] = 0.5f * bc_b[smp] * d[e] - bc_a[smp] * vt[e];                \
        }                                                                      \
    } while (0)

    for (int step = 0; step < NSTEP; step++) {
        FOR_PAIR({
            float2 vv = *(float2*)&v_sm[vidx];
            vt[e0] = vv.x; vt[e0 + 1] = vv.y;
            storeA2(Ahi, Alo, row, cc, x[e0], x[e0 + 1]);
        })
        ACCEL();
        FOR_PAIR({
            float2 t0; t0.x = vt[e0]; t0.y = vt[e0 + 1];
            *(float2*)&xa_sm[vidx] = t0;
            float2 t1; t1.x = g[e0]; t1.y = g[e0 + 1];
            *(float2*)&va_sm[vidx] = t1;
        })
        FOR_PAIR({
            storeA2(Ahi, Alo, row, cc,
                    x[e0] + 0.5f * hs * vt[e0], x[e0 + 1] + 0.5f * hs * vt[e0 + 1]);
            vt[e0]     += 0.5f * hs * g[e0];
            vt[e0 + 1] += 0.5f * hs * g[e0 + 1];
        })
        ACCEL();
        FOR_PAIR({
            float2 xv = *(float2*)&xa_sm[vidx];
            xv.x += 2.0f * vt[e0]; xv.y += 2.0f * vt[e0 + 1];
            *(float2*)&xa_sm[vidx] = xv;
            float2 av = *(float2*)&va_sm[vidx];
            av.x += 2.0f * g[e0]; av.y += 2.0f * g[e0 + 1];
            *(float2*)&va_sm[vidx] = av;
        })
        FOR_PAIR({
            storeA2(Ahi, Alo, row, cc,
                    x[e0] + 0.5f * hs * vt[e0], x[e0 + 1] + 0.5f * hs * vt[e0 + 1]);
            float2 vv = *(float2*)&v_sm[vidx];
            vt[e0]     = vv.x + 0.5f * hs * g[e0];
            vt[e0 + 1] = vv.y + 0.5f * hs * g[e0 + 1];
        })
        ACCEL();
        FOR_PAIR({
            float2 xv = *(float2*)&xa_sm[vidx];
            xv.x += 2.0f * vt[e0]; xv.y += 2.0f * vt[e0 + 1];
            *(float2*)&xa_sm[vidx] = xv;
            float2 av = *(float2*)&va_sm[vidx];
            av.x += 2.0f * g[e0]; av.y += 2.0f * g[e0 + 1];
            *(float2*)&va_sm[vidx] = av;
        })
        FOR_PAIR({
            storeA2(Ahi, Alo, row, cc,
                    x[e0] + hs * vt[e0], x[e0 + 1] + hs * vt[e0 + 1]);
            float2 vv = *(float2*)&v_sm[vidx];
            vt[e0]     = vv.x + hs * g[e0];
            vt[e0 + 1] = vv.y + hs * g[e0 + 1];
        })
        ACCEL();
        {
            float pd[4] = {0.f, 0.f, 0.f, 0.f};
            FOR_PAIR({
                float2 xav = *(float2*)&xa_sm[vidx];
                float2 vav = *(float2*)&va_sm[vidx];
                float2 vv  = *(float2*)&v_sm[vidx];
                x[e0]     += (hs / 6.0f) * (xav.x + vt[e0]);
                x[e0 + 1] += (hs / 6.0f) * (xav.y + vt[e0 + 1]);
                vv.x += (hs / 6.0f) * (vav.x + g[e0]);
                vv.y += (hs / 6.0f) * (vav.y + g[e0 + 1]);
                *(float2*)&v_sm[vidx] = vv;
                float2 zev = *(const float2*)&Z[(size_t)(NB + s0 + row) * DD + cc];
                float dd0 = x[e0] - zev.x;
                float dd1 = x[e0 + 1] - zev.y;
                pd[mf * 2 + jp] += dd0 * dd0 + dd1 * dd1;
            })
#pragma unroll
            for (int sl = 0; sl < 4; sl++) {
                pd[sl] += __shfl_xor_sync(0xffffffffu, pd[sl], 1);
                pd[sl] += __shfl_xor_sync(0xffffffffu, pd[sl], 2);
            }
            if ((lane & 3) == 0) {
#pragma unroll
                for (int sl = 0; sl < 4; sl++) {
                    const int row = (sl >> 1) * 16 + r + 8 * (sl & 1);
                    red_a[wid * 32 + row] = pd[sl];
                }
            }
            __syncthreads();
            if (tid < 32) {
                float tot = 0.f;
#pragma unroll
                for (int w8 = 0; w8 < 8; w8++) tot += red_a[w8 * 32 + tid];
                mymin = fminf(mymin, tot);
            }
            __syncthreads();
        }
    }

    if (tid < 32) mind[s0 + tid] = mymin;
#undef FOR_PAIR
#undef ACCEL
#undef MATVEC
#undef MV_ISSUE
}

// ---------------------------------------------------------------------------
__global__ void reduce_kernel(const float* __restrict__ mind, float* __restrict__ out) {
    __shared__ float sm[1024];
    const int t = threadIdx.x;
    float a = mind[t] + mind[t + 1024] + mind[t + 2048] + mind[t + 3072];
    sm[t] = a;
    __syncthreads();
    for (int off = 512; off > 0; off >>= 1) {
        if (t < off) sm[t] += sm[t + off];
        __syncthreads();
    }
    if (t == 0) out[0] = sm[0] * (1.0f / (float)NB);
}

// ---------------------------------------------------------------------------
// Launch
// ---------------------------------------------------------------------------
extern "C" void kernel_launch(void* const* d_in, const int* in_sizes, int n_in,
                              void* d_out, int out_size) {
    const float* x_start = (const float*)d_in[0];
    const float* x_end   = (const float*)d_in[1];
    const float* noise   = (const float*)d_in[2];
    const float* W1  = (const float*)d_in[3];
    const float* b1  = (const float*)d_in[4];
    const float* W2  = (const float*)d_in[5];
    const float* b2  = (const float*)d_in[6];
    const float* Ww1 = (const float*)d_in[7];
    const float* bw1 = (const float*)d_in[8];
    const float* Ww2 = (const float*)d_in[9];
    const float* bw2 = (const float*)d_in[10];
    const float* Wp1 = (const float*)d_in[11];
    const float* bp1 = (const float*)d_in[12];
    const float* wp2 = (const float*)d_in[13];

    float *Zb, *Vb, *Md;
    cudaGetSymbolAddress((void**)&Zb, g_Z);
    cudaGetSymbolAddress((void**)&Vb, g_V);
    cudaGetSymbolAddress((void**)&Md, g_mind);
    __nv_bfloat16 *Xhi, *Xlo, *Hhi, *Hlo, *Zshi, *Zslo, *HWhi, *HWlo;
    __nv_bfloat16 *W1h, *W1l, *W2h, *W2l, *Ww1h, *Ww1l, *Ww2h, *Ww2l;
    __nv_bfloat16 *Wph, *Wpl, *WTh, *WTl;
    cudaGetSymbolAddress((void**)&Xhi,  g_Xhi);
    cudaGetSymbolAddress((void**)&Xlo,  g_Xlo);
    cudaGetSymbolAddress((void**)&Hhi,  g_Hhi);
    cudaGetSymbolAddress((void**)&Hlo,  g_Hlo);
    cudaGetSymbolAddress((void**)&Zshi, g_Zshi);
    cudaGetSymbolAddress((void**)&Zslo, g_Zslo);
    cudaGetSymbolAddress((void**)&HWhi, g_HWhi);
    cudaGetSymbolAddress((void**)&HWlo, g_HWlo);
    cudaGetSymbolAddress((void**)&W1h,  g_W1Thi);
    cudaGetSymbolAddress((void**)&W1l,  g_W1Tlo);
    cudaGetSymbolAddress((void**)&W2h,  g_W2Thi);
    cudaGetSymbolAddress((void**)&W2l,  g_W2Tlo);
    cudaGetSymbolAddress((void**)&Ww1h, g_Ww1Thi);
    cudaGetSymbolAddress((void**)&Ww1l, g_Ww1Tlo);
    cudaGetSymbolAddress((void**)&Ww2h, g_Ww2Thi);
    cudaGetSymbolAddress((void**)&Ww2l, g_Ww2Tlo);
    cudaGetSymbolAddress((void**)&Wph,  g_Wbhi);
    cudaGetSymbolAddress((void**)&Wpl,  g_Wblo);
    cudaGetSymbolAddress((void**)&WTh,  g_WTbhi);
    cudaGetSymbolAddress((void**)&WTl,  g_WTblo);

    cudaFuncSetAttribute(gemm_mma_kernel<0>,
                         cudaFuncAttributeMaxDynamicSharedMemorySize, GM_SMEM);
    cudaFuncSetAttribute(gemm_mma_kernel<1>,
                         cudaFuncAttributeMaxDynamicSharedMemorySize, GM_SMEM);
    cudaFuncSetAttribute(trace_mma_kernel,
                         cudaFuncAttributeMaxDynamicSharedMemorySize, TR_SMEM_BYTES);

    const int nconv = XB + TB_W1 + TB_W2 + 3 * TB_WW;
    // 0: all conversions
    conv_all_kernel<<<nconv, 256>>>(x_start, x_end, W1, W2, Ww1, Ww2, Wp1,
                                    Xhi, Xlo, W1h, W1l, W2h, W2l,
                                    Ww1h, Ww1l, Ww2h, Ww2l, Wph, Wpl, WTh, WTl);
    // 1: enc1
    gemm_mma_kernel<1><<<dim3(HH / 128, 2 * NB / 128), 256, GM_SMEM>>>(
        Xhi, Xlo, W1h, W1l, b1, nullptr, Hhi, Hlo, 2 * NB, HH, DIN);
    // 2: enc2
    gemm_mma_kernel<0><<<dim3(DD / 128, 2 * NB / 128), 256, GM_SMEM>>>(
        Hhi, Hlo, W2h, W2l, b2, Zb, Zshi, Zslo, NB, DD, HH);
    // 3: wind1
    gemm_mma_kernel<1><<<dim3(DD / 128, NB / 128), 256, GM_SMEM>>>(
        Zshi, Zslo, Ww1h, Ww1l, bw1, nullptr, HWhi, HWlo, NB, DD, DD);
    // 4: wind2
    gemm_mma_kernel<0><<<dim3(DD / 128, NB / 128), 256, GM_SMEM>>>(
        HWhi, HWlo, Ww2h, Ww2l, bw2, Vb, nullptr, nullptr, 0, DD, DD);
    // 5: trace
    trace_mma_kernel<<<NB / SC, 256, TR_SMEM_BYTES>>>(
        Zb, Vb, noise, Wph, Wpl, WTh, WTl, bp1, wp2, Md);
    // 6: mean
    reduce_kernel<<<1, 1024>>>(Md, (float*)d_out);
}